// round 4
// baseline (speedup 1.0000x reference)
#include <cuda_runtime.h>
#include <math.h>

#define S 2048
#define D 4096
#define H 32
#define HD 128
#define KH 128
#define KD 64
#define HEAVY 256
#define RECENT 256
#define NSEL (S - RECENT)   // 1792

// ---------------- scratch (device globals; zero-initialized at load) ----------------
__device__ float g_q[(size_t)S * D];
__device__ float g_k[(size_t)S * D];
__device__ float g_v[(size_t)S * D];
__device__ float g_t1[(size_t)H * S * KH];     // also reused as ctx (needs S*D <= H*S*KH)
__device__ float g_kkA[(size_t)H * S * KD];
__device__ float g_kker[(size_t)H * S * KD];
__device__ float g_probs[(size_t)H * S * S];   // 512 MB
__device__ float g_scores[H * S];
__device__ float g_elim[H * S];

__device__ __forceinline__ float gelu_f(float x) {
    return 0.5f * x * (1.0f + erff(x * 0.7071067811865476f));
}

// ---------------- generic tiled fp32 SGEMM ----------------
// C[m,n] = epilogue( scale * sum_k A[m,k] * B[k,n] )    (B optionally transposed: B[n,k])
// batched over blockIdx.z with element strides sA/sB/sC (and sAux for aux).
// modes: 0 = none, 1 = gelu, 2 = abs(gelu), 3 = |aux[n]| * gelu
// causalMode: 0 none; 1 = logits (skip tiles fully above diagonal, zero n>m);
//             2 = K-loop limited to m0+BM (A's columns > row index are zero).
#define BM 128
#define BN 128
#define BK 16

__global__ __launch_bounds__(256, 2)
void sgemm_kernel(const float* __restrict__ A, const float* __restrict__ B,
                  float* __restrict__ C,
                  int M, int N, int K,
                  int lda, int ldb, int ldc,
                  long long sA, long long sB, long long sC,
                  float scale, int mode, int transB, int causalMode,
                  const float* __restrict__ aux, long long sAux)
{
    int z = blockIdx.z;
    A += (long long)z * sA;
    B += (long long)z * sB;
    C += (long long)z * sC;
    if (aux) aux += (long long)z * sAux;

    int m0 = blockIdx.y * BM;
    int n0 = blockIdx.x * BN;
    if (causalMode == 1 && n0 > m0) return;      // fully above diagonal
    int kEnd = (causalMode == 2) ? min(K, m0 + BM) : K;

    __shared__ float As[BK][BM];
    __shared__ float Bs[BK][BN];

    int tid = threadIdx.x;
    int ty = tid >> 4;    // 0..15
    int tx = tid & 15;    // 0..15

    float acc[8][8];
#pragma unroll
    for (int i = 0; i < 8; i++)
#pragma unroll
        for (int j = 0; j < 8; j++) acc[i][j] = 0.f;

    for (int k0 = 0; k0 < kEnd; k0 += BK) {
        // ---- load A tile: BM x BK (M always multiple of 128, K multiple of 16) ----
#pragma unroll
        for (int it = 0; it < 2; it++) {
            int idx = tid + it * 256;          // 0..511
            int r = idx >> 2;                  // 0..127
            int c = (idx & 3) << 2;            // 0,4,8,12
            float4 a = *reinterpret_cast<const float4*>(&A[(long long)(m0 + r) * lda + k0 + c]);
            As[c + 0][r] = a.x; As[c + 1][r] = a.y; As[c + 2][r] = a.z; As[c + 3][r] = a.w;
        }
        // ---- load B tile: BK x BN ----
        if (!transB) {
#pragma unroll
            for (int it = 0; it < 2; it++) {
                int idx = tid + it * 256;
                int kk = idx >> 5;             // 0..15
                int n  = (idx & 31) << 2;      // 0..124
                float4 b = make_float4(0.f, 0.f, 0.f, 0.f);
                if (n0 + n < N)
                    b = *reinterpret_cast<const float4*>(&B[(long long)(k0 + kk) * ldb + n0 + n]);
                *reinterpret_cast<float4*>(&Bs[kk][n]) = b;
            }
        } else {
#pragma unroll
            for (int it = 0; it < 2; it++) {
                int idx = tid + it * 256;
                int n = idx >> 2;              // 0..127
                int c = (idx & 3) << 2;        // 0,4,8,12
                float4 b = make_float4(0.f, 0.f, 0.f, 0.f);
                if (n0 + n < N)
                    b = *reinterpret_cast<const float4*>(&B[(long long)(n0 + n) * ldb + k0 + c]);
                Bs[c + 0][n] = b.x; Bs[c + 1][n] = b.y; Bs[c + 2][n] = b.z; Bs[c + 3][n] = b.w;
            }
        }
        __syncthreads();

#pragma unroll
        for (int kk = 0; kk < BK; kk++) {
            float ra[8], rb[8];
            *reinterpret_cast<float4*>(&ra[0]) = *reinterpret_cast<const float4*>(&As[kk][ty * 8]);
            *reinterpret_cast<float4*>(&ra[4]) = *reinterpret_cast<const float4*>(&As[kk][ty * 8 + 4]);
            *reinterpret_cast<float4*>(&rb[0]) = *reinterpret_cast<const float4*>(&Bs[kk][tx * 8]);
            *reinterpret_cast<float4*>(&rb[4]) = *reinterpret_cast<const float4*>(&Bs[kk][tx * 8 + 4]);
#pragma unroll
            for (int i = 0; i < 8; i++)
#pragma unroll
                for (int j = 0; j < 8; j++)
                    acc[i][j] += ra[i] * rb[j];
        }
        __syncthreads();
    }

    // ---- epilogue ----
#pragma unroll
    for (int i = 0; i < 8; i++) {
        int m = m0 + ty * 8 + i;
#pragma unroll
        for (int j = 0; j < 8; j++) {
            int n = n0 + tx * 8 + j;
            if (n >= N) continue;
            float v = acc[i][j] * scale;
            if (mode == 1)      v = gelu_f(v);
            else if (mode == 2) v = fabsf(gelu_f(v));
            else if (mode == 3) v = fabsf(aux[n]) * gelu_f(v);
            if (causalMode == 1 && n > m) v = 0.f;
            C[(long long)m * ldc + n] = v;
        }
    }
}

// ---------------- rotary (in-place on q and k) ----------------
__global__ void rotary_kernel(float* __restrict__ q, float* __restrict__ k)
{
    int idx = blockIdx.x * blockDim.x + threadIdx.x;
    if (idx >= S * H * 64) return;
    int i = idx & 63;
    int h = (idx >> 6) & 31;
    int s = idx >> 11;
    // inv_freq = 10000^{-(2i/128)}
    float inv = expf(-9.210340371976184f * (float)i / 64.0f);
    float ang = (float)s * inv;
    float sn, c;
    sincosf(ang, &sn, &c);
    long long base = (long long)s * D + h * HD;
    {
        float x1 = q[base + i], x2 = q[base + 64 + i];
        q[base + i]      = x1 * c - x2 * sn;
        q[base + 64 + i] = x2 * c + x1 * sn;
    }
    {
        float x1 = k[base + i], x2 = k[base + 64 + i];
        k[base + i]      = x1 * c - x2 * sn;
        k[base + 64 + i] = x2 * c + x1 * sn;
    }
}

// ---------------- k_ker interaction: kker = |kkA + (kkA @ ik) * scD2| ----------------
__global__ __launch_bounds__(256)
void interact_kernel(const float* __restrict__ kkA, const float* __restrict__ ik,
                     const float* __restrict__ sc2, float* __restrict__ kker)
{
    int h = blockIdx.y;
    int s0 = blockIdx.x * 64;
    int tid = threadIdx.x;
    __shared__ float sIK[KD][KD];
    __shared__ float sA[64][KD + 1];
    for (int idx = tid; idx < KD * KD; idx += 256)
        sIK[idx >> 6][idx & 63] = ik[(size_t)h * KD * KD + idx];
    for (int idx = tid; idx < 64 * KD; idx += 256) {
        int r = idx >> 6, e = idx & 63;
        sA[r][e] = kkA[((size_t)h * S + s0 + r) * KD + e];
    }
    __syncthreads();
    int r  = tid >> 2;            // 0..63
    int f0 = (tid & 3) * 16;
#pragma unroll
    for (int ff = 0; ff < 16; ff++) {
        int f = f0 + ff;
        float sum = 0.f;
#pragma unroll
        for (int e = 0; e < KD; e++) sum += sA[r][e] * sIK[e][f];
        float val = sA[r][f] + sum * sc2[h * KD + f];
        kker[((size_t)h * S + s0 + r) * KD + f] = fabsf(val);
    }
}

// ---------------- causal softmax (in-place on probs rows) ----------------
__global__ void softmax_kernel(float* __restrict__ probs)
{
    int q = blockIdx.x;
    int h = blockIdx.y;
    float* row = probs + ((size_t)h * S + q) * S;
    int len = q + 1;
    int tid = threadIdx.x;
    __shared__ float red[128];

    float m = -3.402823466e+38f;
    for (int k = tid; k < len; k += 128) m = fmaxf(m, row[k]);
    red[tid] = m; __syncthreads();
    for (int off = 64; off > 0; off >>= 1) {
        if (tid < off) red[tid] = fmaxf(red[tid], red[tid + off]);
        __syncthreads();
    }
    m = red[0]; __syncthreads();

    float sum = 0.f;
    for (int k = tid; k < len; k += 128) {
        float e = expf(row[k] - m);
        sum += e;
        row[k] = e;
    }
    red[tid] = sum; __syncthreads();
    for (int off = 64; off > 0; off >>= 1) {
        if (tid < off) red[tid] += red[tid + off];
        __syncthreads();
    }
    float inv = 1.0f / red[0];
    for (int k = tid; k < len; k += 128) row[k] *= inv;
}

// ---------------- column sums of probs (upper triangle is exactly 0) ----------------
__global__ void scores_kernel(const float* __restrict__ probs, float* __restrict__ scores)
{
    int h = blockIdx.y;
    int k = blockIdx.x * 256 + threadIdx.x;
    const float* p = probs + (size_t)h * S * S + k;
    float s = 0.f;
    for (int q = 0; q < S; q++) s += p[(size_t)q * S];
    scores[h * S + k] = s;
}

// ---------------- top-HEAVY selection -> elim mask ----------------
__global__ __launch_bounds__(256)
void topk_kernel(const float* __restrict__ scores, float* __restrict__ elim)
{
    int h = blockIdx.x;
    int tid = threadIdx.x;
    __shared__ float sv[NSEL];
    __shared__ float rv[256];
    __shared__ int   ri[256];
    for (int j = tid; j < NSEL; j += 256) sv[j] = scores[h * S + j];
    // elim = 1 for s in [0, NSEL] (note s==NSEL stays 1), 0 for recent window
    for (int s = tid; s < S; s += 256) elim[h * S + s] = (s <= NSEL) ? 1.f : 0.f;
    __syncthreads();
    for (int iter = 0; iter < HEAVY; iter++) {
        float best = -1.f; int bi = 0x7fffffff;
        for (int j = tid; j < NSEL; j += 256) {
            float vv = sv[j];
            if (vv > best) { best = vv; bi = j; }
        }
        rv[tid] = best; ri[tid] = bi; __syncthreads();
        for (int off = 128; off > 0; off >>= 1) {
            if (tid < off) {
                float ov = rv[tid + off]; int oi = ri[tid + off];
                if (ov > rv[tid] || (ov == rv[tid] && oi < ri[tid])) { rv[tid] = ov; ri[tid] = oi; }
            }
            __syncthreads();
        }
        if (tid == 0) { int b = ri[0]; elim[h * S + b] = 0.f; sv[b] = -2.f; }
        __syncthreads();
    }
}

// ---------------- H_new / z_new: per head outer-product over eliminated tokens ----------------
__global__ __launch_bounds__(256)
void hnew_kernel(const float* __restrict__ kker, const float* __restrict__ v,
                 const float* __restrict__ elim,
                 float* __restrict__ Hout, float* __restrict__ zout)
{
    int h = blockIdx.x;
    int tid = threadIdx.x;
    __shared__ float skk[32][KD];    // kker * elim
    __shared__ float sv[32][HD];
    int dg = tid & 15;   // d = dg*8 .. +7
    int eg = tid >> 4;   // e = eg*4 .. +3
    float acc[4][8];
#pragma unroll
    for (int e = 0; e < 4; e++)
#pragma unroll
        for (int d = 0; d < 8; d++) acc[e][d] = 0.f;
    float zacc = 0.f;

    const float* kkh = kker + (size_t)h * S * KD;
    const float* vh  = v + h * HD;
    for (int s0 = 0; s0 < S; s0 += 32) {
        for (int idx = tid; idx < 32 * KD; idx += 256) {
            int si = idx >> 6; int e = idx & 63;
            skk[si][e] = kkh[(size_t)(s0 + si) * KD + e] * elim[h * S + s0 + si];
        }
        for (int idx = tid; idx < 32 * HD; idx += 256) {
            int si = idx >> 7; int d = idx & 127;
            sv[si][d] = vh[(size_t)(s0 + si) * D + d];
        }
        __syncthreads();
        if (tid < KD) {
#pragma unroll
            for (int si = 0; si < 32; si++) zacc += skk[si][tid];
        }
#pragma unroll 4
        for (int si = 0; si < 32; si++) {
            float ke[4], vd[8];
#pragma unroll
            for (int e = 0; e < 4; e++) ke[e] = skk[si][eg * 4 + e];
#pragma unroll
            for (int d = 0; d < 8; d++) vd[d] = sv[si][dg * 8 + d];
#pragma unroll
            for (int e = 0; e < 4; e++)
#pragma unroll
                for (int d = 0; d < 8; d++)
                    acc[e][d] += ke[e] * vd[d];
        }
        __syncthreads();
    }
#pragma unroll
    for (int e = 0; e < 4; e++)
#pragma unroll
        for (int d = 0; d < 8; d++)
            Hout[(size_t)h * KD * HD + (eg * 4 + e) * HD + dg * 8 + d] = acc[e][d];
    if (tid < KD) zout[h * KD + tid] = zacc;
}

// ---------------- host side ----------------
static inline void launch_sgemm(const float* A, const float* B, float* C,
                                int M, int N, int K, int lda, int ldb, int ldc,
                                long long sA, long long sB, long long sC, int batch,
                                float scale, int mode, int transB, int causalMode,
                                const float* aux, long long sAux)
{
    dim3 grid((N + BN - 1) / BN, (M + BM - 1) / BM, batch);
    sgemm_kernel<<<grid, 256>>>(A, B, C, M, N, K, lda, ldb, ldc,
                                sA, sB, sC, scale, mode, transB, causalMode, aux, sAux);
}

template <typename T>
static float* sym_addr(T& sym)
{
    void* p = nullptr;
    cudaGetSymbolAddress(&p, sym);
    return (float*)p;
}

extern "C" void kernel_launch(void* const* d_in, const int* in_sizes, int n_in,
                              void* d_out, int out_size)
{
    const float* hs   = (const float*)d_in[0];
    const float* wq   = (const float*)d_in[1];
    const float* wk   = (const float*)d_in[2];
    const float* wv   = (const float*)d_in[3];
    const float* wo   = (const float*)d_in[4];
    const float* kq1  = (const float*)d_in[5];
    const float* kq2  = (const float*)d_in[6];
    const float* kk1  = (const float*)d_in[7];
    const float* kk2  = (const float*)d_in[8];
    const float* scD  = (const float*)d_in[9];
    const float* ik   = (const float*)d_in[10];
    const float* scD2 = (const float*)d_in[11];

    float* out   = (float*)d_out;
    float* outO  = out;                              // (1,S,D)
    float* outH  = out + (size_t)S * D;              // (1,H,KD,HD)
    float* outZ  = outH + (size_t)H * KD * HD;       // (1,H,KD,1)
    float* outQk = outZ + (size_t)H * KD;            // (1,H,S,KD)

    float* q      = sym_addr(g_q);
    float* k      = sym_addr(g_k);
    float* v      = sym_addr(g_v);
    float* t1     = sym_addr(g_t1);
    float* ctx    = t1;                              // reuse: t1 dead before ctx is written
    float* kkA    = sym_addr(g_kkA);
    float* kker   = sym_addr(g_kker);
    float* probs  = sym_addr(g_probs);
    float* scores = sym_addr(g_scores);
    float* elim   = sym_addr(g_elim);

    // 1) QKV projections
    launch_sgemm(hs, wq, q, S, D, D, D, D, D, 0, 0, 0, 1, 1.f, 0, 0, 0, nullptr, 0);
    launch_sgemm(hs, wk, k, S, D, D, D, D, D, 0, 0, 0, 1, 1.f, 0, 0, 0, nullptr, 0);
    launch_sgemm(hs, wv, v, S, D, D, D, D, D, 0, 0, 0, 1, 1.f, 0, 0, 0, nullptr, 0);

    // 2) rotary on q, k
    rotary_kernel<<<(S * H * 64 + 255) / 256, 256>>>(q, k);

    // 3) q_ker path: t1 = gelu(q_h @ kq1_h); q_ker = |gelu(t1 @ kq2_h)|
    launch_sgemm(q, kq1, t1, S, KH, HD, D, KH, KH,
                 HD, (long long)HD * KH, (long long)S * KH, H, 1.f, 1, 0, 0, nullptr, 0);
    launch_sgemm(t1, kq2, outQk, S, KD, KH, KH, KD, KD,
                 (long long)S * KH, (long long)KH * KD, (long long)S * KD, H, 1.f, 2, 0, 0, nullptr, 0);

    // 4) k_ker path: t1 = gelu(k_h @ kk1_h); kkA = |scD| * gelu(t1 @ kk2_h)
    launch_sgemm(k, kk1, t1, S, KH, HD, D, KH, KH,
                 HD, (long long)HD * KH, (long long)S * KH, H, 1.f, 1, 0, 0, nullptr, 0);
    launch_sgemm(t1, kk2, kkA, S, KD, KH, KH, KD, KD,
                 (long long)S * KH, (long long)KH * KD, (long long)S * KD, H, 1.f, 3, 0, 0, scD, KD);

    // 5) kker = |kkA + (kkA @ ik) * scD2|
    {
        dim3 grid(S / 64, H);
        interact_kernel<<<grid, 256>>>(kkA, ik, scD2, kker);
    }

    // 6) causal logits: probs = (q_h @ k_h^T) / sqrt(HD)   (upper of diag tile zeroed)
    launch_sgemm(q, k, probs, S, S, HD, D, D, S,
                 HD, HD, (long long)S * S, H, 0.08838834764831843f, 0, 1, 1, nullptr, 0);

    // 7) softmax in place
    {
        dim3 grid(S, H);
        softmax_kernel<<<grid, 128>>>(probs);
    }

    // 8) scores = column sums
    {
        dim3 grid(S / 256, H);
        scores_kernel<<<grid, 256>>>(probs, scores);
    }

    // 9) top-k -> elim
    topk_kernel<<<H, 256>>>(scores, elim);

    // 10) H_new / z_new
    hnew_kernel<<<H, 256>>>(kker, v, elim, outH, outZ);

    // 11) ctx = probs @ v_h  (K limited by causality; t1 is dead, reused as ctx)
    launch_sgemm(probs, v, ctx, S, HD, S, S, D, D,
                 (long long)S * S, HD, HD, H, 1.f, 0, 0, 2, nullptr, 0);

    // 12) out = ctx @ wo
    launch_sgemm(ctx, wo, outO, S, D, D, D, D, D, 0, 0, 0, 1, 1.f, 0, 0, 0, nullptr, 0);
}

// round 6
// speedup vs baseline: 1.9873x; 1.9873x over previous
#include <cuda_runtime.h>
#include <cuda_bf16.h>
#include <math.h>
#include <stdint.h>

#define S 2048
#define D 4096
#define H 32
#define HD 128
#define KH 128
#define KD 64
#define HEAVY 256
#define RECENT 256
#define NSEL (S - RECENT)   // 1792

typedef __nv_bfloat16 bf16;

// ---------------- scratch (device globals; zero-initialized at load) ----------------
__device__ float g_q[(size_t)S * D];
__device__ float g_k[(size_t)S * D];
__device__ float g_v[(size_t)S * D];
__device__ __align__(16) bf16  g_hsh[(size_t)S * D];
__device__ __align__(16) bf16  g_hsl[(size_t)S * D];
__device__ __align__(16) bf16  g_qh[(size_t)S * D];
__device__ __align__(16) bf16  g_ql[(size_t)S * D];
__device__ __align__(16) bf16  g_kh[(size_t)S * D];
__device__ __align__(16) bf16  g_kl[(size_t)S * D];
__device__ __align__(16) bf16  g_vth[(size_t)H * HD * S];
__device__ __align__(16) bf16  g_vtl[(size_t)H * HD * S];
__device__ __align__(16) bf16  g_wqth[(size_t)D * D];
__device__ __align__(16) bf16  g_wqtl[(size_t)D * D];
__device__ __align__(16) bf16  g_wkth[(size_t)D * D];
__device__ __align__(16) bf16  g_wktl[(size_t)D * D];
__device__ __align__(16) bf16  g_wvth[(size_t)D * D];
__device__ __align__(16) bf16  g_wvtl[(size_t)D * D];
__device__ __align__(16) bf16  g_woth[(size_t)D * D];
__device__ __align__(16) bf16  g_wotl[(size_t)D * D];
__device__ __align__(16) bf16  g_kq1th[(size_t)H * KH * HD];
__device__ __align__(16) bf16  g_kq1tl[(size_t)H * KH * HD];
__device__ __align__(16) bf16  g_kk1th[(size_t)H * KH * HD];
__device__ __align__(16) bf16  g_kk1tl[(size_t)H * KH * HD];
__device__ __align__(16) bf16  g_kq2th[(size_t)H * KD * KH];
__device__ __align__(16) bf16  g_kq2tl[(size_t)H * KD * KH];
__device__ __align__(16) bf16  g_kk2th[(size_t)H * KD * KH];
__device__ __align__(16) bf16  g_kk2tl[(size_t)H * KD * KH];
__device__ __align__(16) bf16  g_t1h[(size_t)H * S * KH];
__device__ __align__(16) bf16  g_t1l[(size_t)H * S * KH];
__device__ float g_kkA[(size_t)H * S * KD];
__device__ float g_kker[(size_t)H * S * KD];
__device__ float g_logits[(size_t)H * S * S];   // 512 MB
__device__ __align__(16) bf16  g_ph[(size_t)H * S * S];       // 256 MB
__device__ __align__(16) bf16  g_pl[(size_t)H * S * S];       // 256 MB
__device__ __align__(16) bf16  g_ctxh[(size_t)S * D];
__device__ __align__(16) bf16  g_ctxl[(size_t)S * D];
__device__ float g_scores[H * S];
__device__ float g_elim[H * S];

__device__ __forceinline__ float gelu_f(float x) {
    return 0.5f * x * (1.0f + erff(x * 0.7071067811865476f));
}

// ============================ PTX helpers ============================
__device__ __forceinline__ uint32_t smem_u32(const void* p) {
    uint32_t a;
    asm("{ .reg .u64 t; cvta.to.shared.u64 t, %1; cvt.u32.u64 %0, t; }" : "=r"(a) : "l"(p));
    return a;
}
__device__ __forceinline__ void cp16(uint32_t dst, const void* src) {
    asm volatile("cp.async.cg.shared.global [%0], [%1], 16;" :: "r"(dst), "l"(src));
}
#define CP_COMMIT() asm volatile("cp.async.commit_group;" ::: "memory")
#define CP_WAIT(n)  asm volatile("cp.async.wait_group %0;" :: "n"(n) : "memory")

#define LDSM4(r, addr) \
    asm volatile("ldmatrix.sync.aligned.m8n8.x4.shared.b16 {%0,%1,%2,%3}, [%4];" \
        : "=r"((r)[0]), "=r"((r)[1]), "=r"((r)[2]), "=r"((r)[3]) : "r"(addr))

#define MMA16816(d, a, b) \
    asm volatile("mma.sync.aligned.m16n8k16.row.col.f32.bf16.bf16.f32 " \
        "{%0,%1,%2,%3}, {%4,%5,%6,%7}, {%8,%9}, {%0,%1,%2,%3};" \
        : "+f"((d)[0]), "+f"((d)[1]), "+f"((d)[2]), "+f"((d)[3]) \
        : "r"((a)[0]), "r"((a)[1]), "r"((a)[2]), "r"((a)[3]), "r"((b)[0]), "r"((b)[1]))

// ============================ HMMA split-bf16 GEMM ============================
// C[m,n] = epi( scale * sum_k (Ah+Al)[m,k] * (Bh+Bl)[n,k] )   (B stored N-major: rows n, cols k)
// modes: 0 none, 1 gelu, 2 abs(gelu), 3 |aux[n]|*gelu
// causal: 0 none; 1 logits (skip n0>m0 tiles, zero n>m); 2 K limited to m0+128.
#define PITCH 80           // bytes per smem row (64 data + 16 pad), conflict-free ldmatrix
#define BK 32              // k elements per stage

template <int NT>
__global__ __launch_bounds__(256)
void hm_gemm(const bf16* __restrict__ Ah, const bf16* __restrict__ Al,
             const bf16* __restrict__ Bh, const bf16* __restrict__ Bl,
             float* __restrict__ Cf, bf16* __restrict__ Ch, bf16* __restrict__ Cl,
             int K, int lda, int ldb, int ldc,
             long long sA, long long sB, long long sC,
             float scale, int mode, int causal,
             const float* __restrict__ aux, long long sAux)
{
    constexpr int WN = NT / 2;         // warp n-extent (4x2 warp grid)
    constexpr int NT8 = WN / 8;        // n8 tiles per warp (8 or 4)
    constexpr int ASZ = 128 * PITCH;   // one A operand per stage
    constexpr int BSZ = NT * PITCH;
    constexpr int STAGE = 2 * ASZ + 2 * BSZ;
    extern __shared__ char smem[];

    const int tid = threadIdx.x;
    const int lane = tid & 31, wrp = tid >> 5;
    const int wm = wrp >> 1, wn = wrp & 1;
    const int m0 = blockIdx.y * 128;
    const int n0 = blockIdx.x * NT;
    if (causal == 1 && n0 > m0) return;

    const long long z = blockIdx.z;
    Ah += z * sA; Al += z * sA;
    Bh += z * sB; Bl += z * sB;
    if (Cf) Cf += z * sC;
    if (Ch) { Ch += z * sC; Cl += z * sC; }
    if (aux) aux += z * sAux;

    const uint32_t sbase = smem_u32(smem);

    float acc[2][NT8][4];
#pragma unroll
    for (int i = 0; i < 2; i++)
#pragma unroll
        for (int j = 0; j < NT8; j++)
#pragma unroll
            for (int t = 0; t < 4; t++) acc[i][j][t] = 0.f;

    const int Keff = (causal == 2) ? (m0 + 128) : K;
    const int nch = Keff / BK;

    auto load_stage = [&](int kc, int st) {
        const int k0 = kc * BK;
        const uint32_t aB = sbase + st * STAGE;
        const uint32_t aL = aB + ASZ;
        const uint32_t bB = aB + 2 * ASZ;
        const uint32_t bL = bB + BSZ;
#pragma unroll
        for (int it = 0; it < 2; it++) {
            int idx = tid + it * 256;                 // 0..511
            int r = idx >> 2;
            int c = idx & 3;
            uint32_t d = r * PITCH + c * 16;
            size_t off = (size_t)(m0 + r) * lda + k0 + c * 8;
            cp16(aB + d, Ah + off);
            cp16(aL + d, Al + off);
        }
#pragma unroll
        for (int it = 0; it < NT / 64; it++) {
            int idx = tid + it * 256;                 // 0..NT*4-1
            int r = idx >> 2;
            int c = idx & 3;
            uint32_t d = r * PITCH + c * 16;
            size_t off = (size_t)(n0 + r) * ldb + k0 + c * 8;
            cp16(bB + d, Bh + off);
            cp16(bL + d, Bl + off);
        }
        CP_COMMIT();
    };

    load_stage(0, 0);
    for (int i = 0; i < nch; i++) {
        const int st = i & 1;
        if (i + 1 < nch) { load_stage(i + 1, 1 - st); CP_WAIT(1); }
        else             { CP_WAIT(0); }
        __syncthreads();

        const uint32_t aB = sbase + st * STAGE;
        const uint32_t aL = aB + ASZ;
        const uint32_t bB = aB + 2 * ASZ;
        const uint32_t bL = bB + BSZ;

#pragma unroll
        for (int ks = 0; ks < 2; ks++) {
            const uint32_t ksoff = ks * 32;           // bytes
            uint32_t ah[2][4], al[2][4];
#pragma unroll
            for (int mt = 0; mt < 2; mt++) {
                int row = wm * 32 + mt * 16 + (lane & 15);
                uint32_t col = ksoff + ((lane & 16) ? 16 : 0);
                LDSM4(ah[mt], aB + row * PITCH + col);
                LDSM4(al[mt], aL + row * PITCH + col);
            }
            uint32_t bh[NT8][2], bl[NT8][2];
#pragma unroll
            for (int jp = 0; jp < NT8 / 2; jp++) {
                int row = wn * WN + jp * 16 + (lane & 7) + ((lane & 16) >> 1);
                uint32_t col = ksoff + ((lane & 8) ? 16 : 0);
                uint32_t r4[4];
                LDSM4(r4, bB + row * PITCH + col);
                bh[2 * jp][0] = r4[0]; bh[2 * jp][1] = r4[1];
                bh[2 * jp + 1][0] = r4[2]; bh[2 * jp + 1][1] = r4[3];
                LDSM4(r4, bL + row * PITCH + col);
                bl[2 * jp][0] = r4[0]; bl[2 * jp][1] = r4[1];
                bl[2 * jp + 1][0] = r4[2]; bl[2 * jp + 1][1] = r4[3];
            }
#pragma unroll
            for (int mt = 0; mt < 2; mt++)
#pragma unroll
                for (int nt = 0; nt < NT8; nt++) MMA16816(acc[mt][nt], ah[mt], bh[nt]);
#pragma unroll
            for (int mt = 0; mt < 2; mt++)
#pragma unroll
                for (int nt = 0; nt < NT8; nt++) MMA16816(acc[mt][nt], ah[mt], bl[nt]);
#pragma unroll
            for (int mt = 0; mt < 2; mt++)
#pragma unroll
                for (int nt = 0; nt < NT8; nt++) MMA16816(acc[mt][nt], al[mt], bh[nt]);
        }
        __syncthreads();
    }

    // ---- epilogue ----
    const int r = lane >> 2, c = (lane & 3) * 2;
#pragma unroll
    for (int mt = 0; mt < 2; mt++) {
#pragma unroll
        for (int nt = 0; nt < NT8; nt++) {
#pragma unroll
            for (int e = 0; e < 4; e++) {
                const int m = m0 + wm * 32 + mt * 16 + r + ((e >> 1) ? 8 : 0);
                const int n = n0 + wn * WN + nt * 8 + c + (e & 1);
                float v = acc[mt][nt][e] * scale;
                if (mode == 1)      v = gelu_f(v);
                else if (mode == 2) v = fabsf(gelu_f(v));
                else if (mode == 3) v = fabsf(aux[n]) * gelu_f(v);
                if (causal == 1 && n > m) v = 0.f;
                const size_t o = (size_t)m * ldc + n;
                if (Cf) Cf[o] = v;
                if (Ch) {
                    bf16 hv = __float2bfloat16(v);
                    Ch[o] = hv;
                    Cl[o] = __float2bfloat16(v - __bfloat162float(hv));
                }
            }
        }
    }
}

// ---------------- split fp32 -> bf16 hi/lo ----------------
__global__ void split_kernel(const float* __restrict__ x, bf16* __restrict__ hi,
                             bf16* __restrict__ lo, int n)
{
    int i = blockIdx.x * blockDim.x + threadIdx.x;
    if (i >= n) return;
    float v = x[i];
    bf16 h = __float2bfloat16(v);
    hi[i] = h;
    lo[i] = __float2bfloat16(v - __bfloat162float(h));
}

// ---------------- split + transpose: in (R x Cc, ldin) -> out (Cc x R, ld=R) ----------------
__global__ void splitT_kernel(const float* __restrict__ in, bf16* __restrict__ oh,
                              bf16* __restrict__ ol, int R, int ldin,
                              long long sIn, long long sOut)
{
    in += (long long)blockIdx.z * sIn;
    oh += (long long)blockIdx.z * sOut;
    ol += (long long)blockIdx.z * sOut;
    __shared__ float t[32][33];
    int r0 = blockIdx.y * 32, c0 = blockIdx.x * 32;
    int tx = threadIdx.x, ty = threadIdx.y;  // (32, 8)
#pragma unroll
    for (int i = 0; i < 4; i++)
        t[ty + 8 * i][tx] = in[(size_t)(r0 + ty + 8 * i) * ldin + c0 + tx];
    __syncthreads();
#pragma unroll
    for (int i = 0; i < 4; i++) {
        int oc = ty + 8 * i;
        float v = t[tx][oc];                 // = in[r0+tx][c0+oc]
        size_t o = (size_t)(c0 + oc) * R + r0 + tx;
        bf16 h = __float2bfloat16(v);
        oh[o] = h;
        ol[o] = __float2bfloat16(v - __bfloat162float(h));
    }
}

// ---------------- rotary: fp32 q,k -> rotated bf16 hi/lo splits ----------------
__global__ void rotary_split_kernel(const float* __restrict__ q, const float* __restrict__ k,
                                    bf16* __restrict__ qh, bf16* __restrict__ ql,
                                    bf16* __restrict__ kh, bf16* __restrict__ kl)
{
    int idx = blockIdx.x * blockDim.x + threadIdx.x;
    if (idx >= S * H * 64) return;
    int i = idx & 63;
    int h = (idx >> 6) & 31;
    int s = idx >> 11;
    float inv = expf(-9.210340371976184f * (float)i / 64.0f);
    float ang = (float)s * inv;
    float sn, c;
    sincosf(ang, &sn, &c);
    long long base = (long long)s * D + h * HD;
    {
        float x1 = q[base + i], x2 = q[base + 64 + i];
        float r1 = x1 * c - x2 * sn;
        float r2 = x2 * c + x1 * sn;
        bf16 h1 = __float2bfloat16(r1); qh[base + i] = h1;      ql[base + i] = __float2bfloat16(r1 - __bfloat162float(h1));
        bf16 h2 = __float2bfloat16(r2); qh[base + 64 + i] = h2; ql[base + 64 + i] = __float2bfloat16(r2 - __bfloat162float(h2));
    }
    {
        float x1 = k[base + i], x2 = k[base + 64 + i];
        float r1 = x1 * c - x2 * sn;
        float r2 = x2 * c + x1 * sn;
        bf16 h1 = __float2bfloat16(r1); kh[base + i] = h1;      kl[base + i] = __float2bfloat16(r1 - __bfloat162float(h1));
        bf16 h2 = __float2bfloat16(r2); kh[base + 64 + i] = h2; kl[base + 64 + i] = __float2bfloat16(r2 - __bfloat162float(h2));
    }
}

// ---------------- k_ker interaction: kker = |kkA + (kkA @ ik) * scD2| ----------------
__global__ __launch_bounds__(256)
void interact_kernel(const float* __restrict__ kkA, const float* __restrict__ ik,
                     const float* __restrict__ sc2, float* __restrict__ kker)
{
    int h = blockIdx.y;
    int s0 = blockIdx.x * 64;
    int tid = threadIdx.x;
    __shared__ float sIK[KD][KD];
    __shared__ float sA[64][KD + 1];
    for (int idx = tid; idx < KD * KD; idx += 256)
        sIK[idx >> 6][idx & 63] = ik[(size_t)h * KD * KD + idx];
    for (int idx = tid; idx < 64 * KD; idx += 256) {
        int r = idx >> 6, e = idx & 63;
        sA[r][e] = kkA[((size_t)h * S + s0 + r) * KD + e];
    }
    __syncthreads();
    int r = tid >> 2;
    int f0 = (tid & 3) * 16;
#pragma unroll
    for (int ff = 0; ff < 16; ff++) {
        int f = f0 + ff;
        float sum = 0.f;
#pragma unroll
        for (int e = 0; e < KD; e++) sum += sA[r][e] * sIK[e][f];
        float val = sA[r][f] + sum * sc2[h * KD + f];
        kker[((size_t)h * S + s0 + r) * KD + f] = fabsf(val);
    }
}

// ---------------- causal softmax: fp32 logits -> bf16 hi/lo probs ----------------
__global__ void softmax_kernel(float* __restrict__ logits, bf16* __restrict__ ph, bf16* __restrict__ pl)
{
    int q = blockIdx.x;
    int h = blockIdx.y;
    float* row = logits + ((size_t)h * S + q) * S;
    bf16* rh = ph + ((size_t)h * S + q) * S;
    bf16* rl = pl + ((size_t)h * S + q) * S;
    int len = q + 1;
    int tid = threadIdx.x;
    __shared__ float red[128];

    float m = -3.402823466e+38f;
    for (int k = tid; k < len; k += 128) m = fmaxf(m, row[k]);
    red[tid] = m; __syncthreads();
    for (int off = 64; off > 0; off >>= 1) {
        if (tid < off) red[tid] = fmaxf(red[tid], red[tid + off]);
        __syncthreads();
    }
    m = red[0]; __syncthreads();

    float sum = 0.f;
    for (int k = tid; k < len; k += 128) {
        float e = expf(row[k] - m);
        sum += e;
        row[k] = e;
    }
    red[tid] = sum; __syncthreads();
    for (int off = 64; off > 0; off >>= 1) {
        if (tid < off) red[tid] += red[tid + off];
        __syncthreads();
    }
    float inv = 1.0f / red[0];
    for (int k = tid; k < len; k += 128) {
        float p = row[k] * inv;
        bf16 hv = __float2bfloat16(p);
        rh[k] = hv;
        rl[k] = __float2bfloat16(p - __bfloat162float(hv));
    }
}

// ---------------- column sums of probs (upper triangle is exactly 0) ----------------
__global__ void scores_kernel(const bf16* __restrict__ ph, const bf16* __restrict__ pl,
                              float* __restrict__ scores)
{
    int h = blockIdx.y;
    int k = blockIdx.x * 256 + threadIdx.x;
    const bf16* p1 = ph + (size_t)h * S * S + k;
    const bf16* p2 = pl + (size_t)h * S * S + k;
    float s = 0.f;
    for (int q = 0; q < S; q++)
        s += __bfloat162float(p1[(size_t)q * S]) + __bfloat162float(p2[(size_t)q * S]);
    scores[h * S + k] = s;
}

// ---------------- top-HEAVY selection -> elim mask ----------------
__global__ __launch_bounds__(256)
void topk_kernel(const float* __restrict__ scores, float* __restrict__ elim)
{
    int h = blockIdx.x;
    int tid = threadIdx.x;
    __shared__ float sv[NSEL];
    __shared__ float rv[256];
    __shared__ int   ri[256];
    for (int j = tid; j < NSEL; j += 256) sv[j] = scores[h * S + j];
    for (int s = tid; s < S; s += 256) elim[h * S + s] = (s <= NSEL) ? 1.f : 0.f;
    __syncthreads();
    for (int iter = 0; iter < HEAVY; iter++) {
        float best = -1.f; int bi = 0x7fffffff;
        for (int j = tid; j < NSEL; j += 256) {
            float vv = sv[j];
            if (vv > best) { best = vv; bi = j; }
        }
        rv[tid] = best; ri[tid] = bi; __syncthreads();
        for (int off = 128; off > 0; off >>= 1) {
            if (tid < off) {
                float ov = rv[tid + off]; int oi = ri[tid + off];
                if (ov > rv[tid] || (ov == rv[tid] && oi < ri[tid])) { rv[tid] = ov; ri[tid] = oi; }
            }
            __syncthreads();
        }
        if (tid == 0) { int b = ri[0]; elim[h * S + b] = 0.f; sv[b] = -2.f; }
        __syncthreads();
    }
}

// ---------------- H_new / z_new ----------------
__global__ __launch_bounds__(256)
void hnew_kernel(const float* __restrict__ kker, const float* __restrict__ v,
                 const float* __restrict__ elim,
                 float* __restrict__ Hout, float* __restrict__ zout)
{
    int h = blockIdx.x;
    int tid = threadIdx.x;
    __shared__ float skk[32][KD];
    __shared__ float sv[32][HD];
    int dg = tid & 15;
    int eg = tid >> 4;
    float acc[4][8];
#pragma unroll
    for (int e = 0; e < 4; e++)
#pragma unroll
        for (int d = 0; d < 8; d++) acc[e][d] = 0.f;
    float zacc = 0.f;

    const float* kkh = kker + (size_t)h * S * KD;
    const float* vh  = v + h * HD;
    for (int s0 = 0; s0 < S; s0 += 32) {
        for (int idx = tid; idx < 32 * KD; idx += 256) {
            int si = idx >> 6; int e = idx & 63;
            skk[si][e] = kkh[(size_t)(s0 + si) * KD + e] * elim[h * S + s0 + si];
        }
        for (int idx = tid; idx < 32 * HD; idx += 256) {
            int si = idx >> 7; int d = idx & 127;
            sv[si][d] = vh[(size_t)(s0 + si) * D + d];
        }
        __syncthreads();
        if (tid < KD) {
#pragma unroll
            for (int si = 0; si < 32; si++) zacc += skk[si][tid];
        }
#pragma unroll 4
        for (int si = 0; si < 32; si++) {
            float ke[4], vd[8];
#pragma unroll
            for (int e = 0; e < 4; e++) ke[e] = skk[si][eg * 4 + e];
#pragma unroll
            for (int d = 0; d < 8; d++) vd[d] = sv[si][dg * 8 + d];
#pragma unroll
            for (int e = 0; e < 4; e++)
#pragma unroll
                for (int d = 0; d < 8; d++)
                    acc[e][d] += ke[e] * vd[d];
        }
        __syncthreads();
    }
#pragma unroll
    for (int e = 0; e < 4; e++)
#pragma unroll
        for (int d = 0; d < 8; d++)
            Hout[(size_t)h * KD * HD + (eg * 4 + e) * HD + dg * 8 + d] = acc[e][d];
    if (tid < KD) zout[h * KD + tid] = zacc;
}

// ---------------- host side ----------------
template <typename T>
static float* sym_f(T& sym) { void* p = nullptr; cudaGetSymbolAddress(&p, sym); return (float*)p; }
template <typename T>
static bf16* sym_b(T& sym) { void* p = nullptr; cudaGetSymbolAddress(&p, sym); return (bf16*)p; }

static const int SMEM128 = 2 * (2 * 128 * PITCH + 2 * 128 * PITCH);  // 81920
static const int SMEM64  = 2 * (2 * 128 * PITCH + 2 * 64 * PITCH);   // 61440

static inline void gemm128(const bf16* Ah, const bf16* Al, const bf16* Bh, const bf16* Bl,
                           float* Cf, bf16* Ch, bf16* Cl,
                           int M, int N, int K, int lda, int ldb, int ldc,
                           long long sA, long long sB, long long sC, int batch,
                           float scale, int mode, int causal,
                           const float* aux = nullptr, long long sAux = 0)
{
    dim3 grid(N / 128, M / 128, batch);
    hm_gemm<128><<<grid, 256, SMEM128>>>(Ah, Al, Bh, Bl, Cf, Ch, Cl, K, lda, ldb, ldc,
                                         sA, sB, sC, scale, mode, causal, aux, sAux);
}
static inline void gemm64(const bf16* Ah, const bf16* Al, const bf16* Bh, const bf16* Bl,
                          float* Cf, bf16* Ch, bf16* Cl,
                          int M, int N, int K, int lda, int ldb, int ldc,
                          long long sA, long long sB, long long sC, int batch,
                          float scale, int mode, int causal,
                          const float* aux = nullptr, long long sAux = 0)
{
    dim3 grid(N / 64, M / 128, batch);
    hm_gemm<64><<<grid, 256, SMEM64>>>(Ah, Al, Bh, Bl, Cf, Ch, Cl, K, lda, ldb, ldc,
                                       sA, sB, sC, scale, mode, causal, aux, sAux);
}

extern "C" void kernel_launch(void* const* d_in, const int* in_sizes, int n_in,
                              void* d_out, int out_size)
{
    const float* hs   = (const float*)d_in[0];
    const float* wq   = (const float*)d_in[1];
    const float* wk   = (const float*)d_in[2];
    const float* wv   = (const float*)d_in[3];
    const float* wo   = (const float*)d_in[4];
    const float* kq1  = (const float*)d_in[5];
    const float* kq2  = (const float*)d_in[6];
    const float* kk1  = (const float*)d_in[7];
    const float* kk2  = (const float*)d_in[8];
    const float* scD  = (const float*)d_in[9];
    const float* ik   = (const float*)d_in[10];
    const float* scD2 = (const float*)d_in[11];

    float* out   = (float*)d_out;
    float* outO  = out;
    float* outH  = out + (size_t)S * D;
    float* outZ  = outH + (size_t)H * KD * HD;
    float* outQk = outZ + (size_t)H * KD;

    float* q = sym_f(g_q);  float* k = sym_f(g_k);  float* v = sym_f(g_v);
    bf16 *hsh = sym_b(g_hsh), *hsl = sym_b(g_hsl);
    bf16 *qh = sym_b(g_qh), *ql = sym_b(g_ql), *kh = sym_b(g_kh), *kl = sym_b(g_kl);
    bf16 *vth = sym_b(g_vth), *vtl = sym_b(g_vtl);
    bf16 *wqth = sym_b(g_wqth), *wqtl = sym_b(g_wqtl);
    bf16 *wkth = sym_b(g_wkth), *wktl = sym_b(g_wktl);
    bf16 *wvth = sym_b(g_wvth), *wvtl = sym_b(g_wvtl);
    bf16 *woth = sym_b(g_woth), *wotl = sym_b(g_wotl);
    bf16 *kq1th = sym_b(g_kq1th), *kq1tl = sym_b(g_kq1tl);
    bf16 *kk1th = sym_b(g_kk1th), *kk1tl = sym_b(g_kk1tl);
    bf16 *kq2th = sym_b(g_kq2th), *kq2tl = sym_b(g_kq2tl);
    bf16 *kk2th = sym_b(g_kk2th), *kk2tl = sym_b(g_kk2tl);
    bf16 *t1h = sym_b(g_t1h), *t1l = sym_b(g_t1l);
    bf16 *ph = sym_b(g_ph), *pl = sym_b(g_pl);
    bf16 *ctxh = sym_b(g_ctxh), *ctxl = sym_b(g_ctxl);
    float* kkA = sym_f(g_kkA);
    float* kker = sym_f(g_kker);
    float* logits = sym_f(g_logits);
    float* scores = sym_f(g_scores);
    float* elim = sym_f(g_elim);

    cudaFuncSetAttribute(hm_gemm<128>, cudaFuncAttributeMaxDynamicSharedMemorySize, SMEM128);
    cudaFuncSetAttribute(hm_gemm<64>,  cudaFuncAttributeMaxDynamicSharedMemorySize, SMEM64);

    // ---- 0) operand prep: splits (+ transposes for B operands) ----
    split_kernel<<<(S * D + 255) / 256, 256>>>(hs, hsh, hsl, S * D);
    {
        dim3 g(D / 32, D / 32, 1), b(32, 8);
        splitT_kernel<<<g, b>>>(wq, wqth, wqtl, D, D, 0, 0);
        splitT_kernel<<<g, b>>>(wk, wkth, wktl, D, D, 0, 0);
        splitT_kernel<<<g, b>>>(wv, wvth, wvtl, D, D, 0, 0);
        splitT_kernel<<<g, b>>>(wo, woth, wotl, D, D, 0, 0);
    }
    {
        dim3 g(KH / 32, HD / 32, H), b(32, 8);
        splitT_kernel<<<g, b>>>(kq1, kq1th, kq1tl, HD, KH, (long long)HD * KH, (long long)KH * HD);
        splitT_kernel<<<g, b>>>(kk1, kk1th, kk1tl, HD, KH, (long long)HD * KH, (long long)KH * HD);
    }
    {
        dim3 g(KD / 32, KH / 32, H), b(32, 8);
        splitT_kernel<<<g, b>>>(kq2, kq2th, kq2tl, KH, KD, (long long)KH * KD, (long long)KD * KH);
        splitT_kernel<<<g, b>>>(kk2, kk2th, kk2tl, KH, KD, (long long)KH * KD, (long long)KD * KH);
    }

    // ---- 1) QKV projections (fp32 out) ----
    gemm128(hsh, hsl, wqth, wqtl, q, nullptr, nullptr, S, D, D, D, D, D, 0, 0, 0, 1, 1.f, 0, 0);
    gemm128(hsh, hsl, wkth, wktl, k, nullptr, nullptr, S, D, D, D, D, D, 0, 0, 0, 1, 1.f, 0, 0);
    gemm128(hsh, hsl, wvth, wvtl, v, nullptr, nullptr, S, D, D, D, D, D, 0, 0, 0, 1, 1.f, 0, 0);

    // ---- 2) rotary -> split q,k ----
    rotary_split_kernel<<<(S * H * 64 + 255) / 256, 256>>>(q, k, qh, ql, kh, kl);

    // ---- 3) v^T split per head (B operand of probs@v) ----
    {
        dim3 g(HD / 32, S / 32, H), b(32, 8);
        splitT_kernel<<<g, b>>>(v, vth, vtl, S, D, (long long)HD, (long long)HD * S);
    }

    // ---- 4) q_ker path ----
    gemm128(qh, ql, kq1th, kq1tl, nullptr, t1h, t1l, S, KH, HD, D, HD, KH,
            HD, (long long)KH * HD, (long long)S * KH, H, 1.f, 1, 0);
    gemm64(t1h, t1l, kq2th, kq2tl, outQk, nullptr, nullptr, S, KD, KH, KH, KH, KD,
           (long long)S * KH, (long long)KD * KH, (long long)S * KD, H, 1.f, 2, 0);

    // ---- 5) k_ker path (reuse t1) ----
    gemm128(kh, kl, kk1th, kk1tl, nullptr, t1h, t1l, S, KH, HD, D, HD, KH,
            HD, (long long)KH * HD, (long long)S * KH, H, 1.f, 1, 0);
    gemm64(t1h, t1l, kk2th, kk2tl, kkA, nullptr, nullptr, S, KD, KH, KH, KH, KD,
           (long long)S * KH, (long long)KD * KH, (long long)S * KD, H, 1.f, 3, 0, scD, KD);

    // ---- 6) interaction -> kker ----
    {
        dim3 grid(S / 64, H);
        interact_kernel<<<grid, 256>>>(kkA, ik, scD2, kker);
    }

    // ---- 7) causal logits ----
    gemm128(qh, ql, kh, kl, logits, nullptr, nullptr, S, S, HD, D, D, S,
            HD, HD, (long long)S * S, H, 0.08838834764831843f, 0, 1);

    // ---- 8) softmax -> probs hi/lo ----
    {
        dim3 grid(S, H);
        softmax_kernel<<<grid, 128>>>(logits, ph, pl);
    }

    // ---- 9) scores / topk / hnew ----
    {
        dim3 grid(S / 256, H);
        scores_kernel<<<grid, 256>>>(ph, pl, scores);
    }
    topk_kernel<<<H, 256>>>(scores, elim);
    hnew_kernel<<<H, 256>>>(kker, v, elim, outH, outZ);

    // ---- 10) ctx = probs @ v (causal K-limit), split out ----
    gemm128(ph, pl, vth, vtl, nullptr, ctxh, ctxl, S, HD, S, S, S, D,
            (long long)S * S, (long long)HD * S, (long long)HD, H, 1.f, 0, 2);

    // ---- 11) out = ctx @ wo ----
    gemm128(ctxh, ctxl, woth, wotl, outO, nullptr, nullptr, S, D, D, D, D, D,
            0, 0, 0, 1, 1.f, 0, 0);
}

// round 9
// speedup vs baseline: 2.7890x; 1.4035x over previous
#include <cuda_runtime.h>
#include <cuda_bf16.h>
#include <cuda_fp16.h>
#include <math.h>
#include <float.h>
#include <stdint.h>

#define S 2048
#define D 4096
#define H 32
#define HD 128
#define KH 128
#define KD 64
#define HEAVY 256
#define RECENT 256
#define NSEL (S - RECENT)   // 1792

typedef __nv_bfloat16 bf16;
typedef __half fp16;

// ---------------- scratch (device globals; zero-initialized at load) ----------------
__device__ float g_q[(size_t)S * D];
__device__ float g_k[(size_t)S * D];
__device__ float g_v[(size_t)S * D];
__device__ __align__(16) bf16 g_hsh[(size_t)S * D];
__device__ __align__(16) bf16 g_hsl[(size_t)S * D];
__device__ __align__(16) fp16 g_hs16[(size_t)S * D];
__device__ __align__(16) bf16 g_qh[(size_t)S * D];
__device__ __align__(16) bf16 g_ql[(size_t)S * D];
__device__ __align__(16) bf16 g_kh[(size_t)S * D];
__device__ __align__(16) bf16 g_kl[(size_t)S * D];
__device__ __align__(16) fp16 g_q16[(size_t)S * D];
__device__ __align__(16) fp16 g_k16[(size_t)S * D];
__device__ __align__(16) fp16 g_vt16[(size_t)H * HD * S];
__device__ __align__(16) bf16 g_wqth[(size_t)D * D];
__device__ __align__(16) bf16 g_wqtl[(size_t)D * D];
__device__ __align__(16) bf16 g_wkth[(size_t)D * D];
__device__ __align__(16) bf16 g_wktl[(size_t)D * D];
__device__ __align__(16) fp16 g_wvt16[(size_t)D * D];
__device__ __align__(16) fp16 g_wot16[(size_t)D * D];
__device__ __align__(16) fp16 g_kq1t[(size_t)H * KH * HD];
__device__ __align__(16) fp16 g_kk1t[(size_t)H * KH * HD];
__device__ __align__(16) fp16 g_kq2t[(size_t)H * KD * KH];
__device__ __align__(16) fp16 g_kk2t[(size_t)H * KD * KH];
__device__ __align__(16) fp16 g_t116[(size_t)H * S * KH];
__device__ float g_kkA[(size_t)H * S * KD];
__device__ float g_kker[(size_t)H * S * KD];
__device__ float g_logits[(size_t)H * S * S];   // 512 MB
__device__ __align__(16) fp16 g_ph[(size_t)H * S * S];        // 256 MB
__device__ __align__(16) fp16 g_pl[(size_t)H * S * S];        // 256 MB
__device__ __align__(16) fp16 g_ctx16[(size_t)S * D];
__device__ float g_scores[H * S];
__device__ float g_elim[H * S];

__device__ __forceinline__ float gelu_f(float x) {
    return 0.5f * x * (1.0f + erff(x * 0.7071067811865476f));
}

// ============================ PTX helpers ============================
__device__ __forceinline__ uint32_t smem_u32(const void* p) {
    uint32_t a;
    asm("{ .reg .u64 t; cvta.to.shared.u64 t, %1; cvt.u32.u64 %0, t; }" : "=r"(a) : "l"(p));
    return a;
}
__device__ __forceinline__ void cp16(uint32_t dst, const void* src) {
    asm volatile("cp.async.cg.shared.global [%0], [%1], 16;" :: "r"(dst), "l"(src));
}
#define CP_COMMIT() asm volatile("cp.async.commit_group;" ::: "memory")
#define CP_WAIT(n)  asm volatile("cp.async.wait_group %0;" :: "n"(n) : "memory")

#define LDSM4(r, addr) \
    asm volatile("ldmatrix.sync.aligned.m8n8.x4.shared.b16 {%0,%1,%2,%3}, [%4];" \
        : "=r"((r)[0]), "=r"((r)[1]), "=r"((r)[2]), "=r"((r)[3]) : "r"(addr))

#define MMA_BF(d, a, b) \
    asm volatile("mma.sync.aligned.m16n8k16.row.col.f32.bf16.bf16.f32 " \
        "{%0,%1,%2,%3}, {%4,%5,%6,%7}, {%8,%9}, {%0,%1,%2,%3};" \
        : "+f"((d)[0]), "+f"((d)[1]), "+f"((d)[2]), "+f"((d)[3]) \
        : "r"((a)[0]), "r"((a)[1]), "r"((a)[2]), "r"((a)[3]), "r"((b)[0]), "r"((b)[1]))

#define MMA_FP(d, a, b) \
    asm volatile("mma.sync.aligned.m16n8k16.row.col.f32.f16.f16.f32 " \
        "{%0,%1,%2,%3}, {%4,%5,%6,%7}, {%8,%9}, {%0,%1,%2,%3};" \
        : "+f"((d)[0]), "+f"((d)[1]), "+f"((d)[2]), "+f"((d)[3]) \
        : "r"((a)[0]), "r"((a)[1]), "r"((a)[2]), "r"((a)[3]), "r"((b)[0]), "r"((b)[1]))

// ============================ HMMA multi-pass GEMM ============================
// C[m,n] = epi( scale * sum_k (A0 [+A1])[m,k] * (B0 [+B1])[n,k] )  (B N-major)
// passes: (a0,b0); +(a0,b1) if NB==2; +(a1,b0) if NA==2.   (lo*lo dropped)
// modes: 0 none, 1 gelu, 2 abs(gelu), 3 |aux[n]|*gelu
// causal: 0 none; 1 logits (skip n0>m0 tiles, zero n>m); 2 K limited to m0+128.
#define PITCH 144          // 128 data bytes + 16 pad per smem row
#define BKE 64             // k elements per stage

template <int NT, int NA, int NB, bool BF>
__global__ __launch_bounds__(256)
void hm_gemm(const uint16_t* __restrict__ A0, const uint16_t* __restrict__ A1,
             const uint16_t* __restrict__ B0, const uint16_t* __restrict__ B1,
             float* __restrict__ Cf, fp16* __restrict__ C16,
             int K, int lda, int ldb, int ldc,
             long long sA, long long sB, long long sC,
             float scale, int mode, int causal,
             const float* __restrict__ aux, long long sAux)
{
    constexpr int WN = NT / 2;         // warp n-extent (4x2 warp grid)
    constexpr int NT8 = WN / 8;        // n8 tiles per warp
    constexpr int ASZ = 128 * PITCH;
    constexpr int BSZ = NT * PITCH;
    constexpr int STAGE = NA * ASZ + NB * BSZ;
    extern __shared__ char smem[];

    const int tid = threadIdx.x;
    const int lane = tid & 31, wrp = tid >> 5;
    const int wm = wrp >> 1, wn = wrp & 1;
    const int m0 = blockIdx.y * 128;
    const int n0 = blockIdx.x * NT;
    if (causal == 1 && n0 > m0) return;

    const long long z = blockIdx.z;
    const uint16_t* Aop[2] = { A0 + z * sA, A1 ? A1 + z * sA : nullptr };
    const uint16_t* Bop[2] = { B0 + z * sB, B1 ? B1 + z * sB : nullptr };
    if (Cf) Cf += z * sC;
    if (C16) C16 += z * sC;
    if (aux) aux += z * sAux;

    const uint32_t sbase = smem_u32(smem);

    float acc[2][NT8][4];
#pragma unroll
    for (int i = 0; i < 2; i++)
#pragma unroll
        for (int j = 0; j < NT8; j++)
#pragma unroll
            for (int t = 0; t < 4; t++) acc[i][j][t] = 0.f;

    const int Keff = (causal == 2) ? (m0 + 128) : K;
    const int nch = Keff / BKE;

    auto load_stage = [&](int kc, int st) {
        const int k0 = kc * BKE;
        const uint32_t base = sbase + st * STAGE;
#pragma unroll
        for (int a = 0; a < NA; a++) {
            const uint32_t ab = base + a * ASZ;
#pragma unroll
            for (int it = 0; it < 4; it++) {
                int idx = tid + it * 256;              // 0..1023
                int r = idx >> 3, cb = (idx & 7) * 16;
                cp16(ab + r * PITCH + cb, Aop[a] + (size_t)(m0 + r) * lda + k0 + (cb >> 1));
            }
        }
#pragma unroll
        for (int b = 0; b < NB; b++) {
            const uint32_t bb = base + NA * ASZ + b * BSZ;
#pragma unroll
            for (int it = 0; it < NT / 32; it++) {
                int idx = tid + it * 256;
                int r = idx >> 3, cb = (idx & 7) * 16;
                cp16(bb + r * PITCH + cb, Bop[b] + (size_t)(n0 + r) * ldb + k0 + (cb >> 1));
            }
        }
        CP_COMMIT();
    };

    load_stage(0, 0);
    for (int i = 0; i < nch; i++) {
        const int st = i & 1;
        if (i + 1 < nch) { load_stage(i + 1, 1 - st); CP_WAIT(1); }
        else             { CP_WAIT(0); }
        __syncthreads();

        const uint32_t base = sbase + st * STAGE;

#pragma unroll
        for (int ks = 0; ks < 4; ks++) {
            const uint32_t ksoff = ks * 32;           // bytes (16 elems)
            uint32_t af[NA][2][4];
#pragma unroll
            for (int a = 0; a < NA; a++) {
#pragma unroll
                for (int mt = 0; mt < 2; mt++) {
                    int row = wm * 32 + mt * 16 + (lane & 15);
                    uint32_t col = ksoff + ((lane & 16) ? 16 : 0);
                    LDSM4(af[a][mt], base + a * ASZ + row * PITCH + col);
                }
            }
            uint32_t bfr[NB][NT8][2];
#pragma unroll
            for (int b = 0; b < NB; b++) {
#pragma unroll
                for (int jp = 0; jp < NT8 / 2; jp++) {
                    int row = wn * WN + jp * 16 + (lane & 7) + ((lane & 16) >> 1);
                    uint32_t col = ksoff + ((lane & 8) ? 16 : 0);
                    uint32_t r4[4];
                    LDSM4(r4, base + NA * ASZ + b * BSZ + row * PITCH + col);
                    bfr[b][2 * jp][0] = r4[0]; bfr[b][2 * jp][1] = r4[1];
                    bfr[b][2 * jp + 1][0] = r4[2]; bfr[b][2 * jp + 1][1] = r4[3];
                }
            }
            // pass 1: a0*b0
#pragma unroll
            for (int mt = 0; mt < 2; mt++)
#pragma unroll
                for (int nt = 0; nt < NT8; nt++) {
                    if (BF) { MMA_BF(acc[mt][nt], af[0][mt], bfr[0][nt]); }
                    else    { MMA_FP(acc[mt][nt], af[0][mt], bfr[0][nt]); }
                }
            // pass 2: a0*b1
            if (NB == 2) {
#pragma unroll
                for (int mt = 0; mt < 2; mt++)
#pragma unroll
                    for (int nt = 0; nt < NT8; nt++) {
                        if (BF) { MMA_BF(acc[mt][nt], af[0][mt], bfr[NB - 1][nt]); }
                        else    { MMA_FP(acc[mt][nt], af[0][mt], bfr[NB - 1][nt]); }
                    }
            }
            // pass 3: a1*b0
            if (NA == 2) {
#pragma unroll
                for (int mt = 0; mt < 2; mt++)
#pragma unroll
                    for (int nt = 0; nt < NT8; nt++) {
                        if (BF) { MMA_BF(acc[mt][nt], af[NA - 1][mt], bfr[0][nt]); }
                        else    { MMA_FP(acc[mt][nt], af[NA - 1][mt], bfr[0][nt]); }
                    }
            }
        }
        __syncthreads();
    }

    // ---- epilogue ----
    const int r = lane >> 2, c = (lane & 3) * 2;
#pragma unroll
    for (int mt = 0; mt < 2; mt++) {
#pragma unroll
        for (int nt = 0; nt < NT8; nt++) {
#pragma unroll
            for (int e = 0; e < 4; e++) {
                const int m = m0 + wm * 32 + mt * 16 + r + ((e >> 1) ? 8 : 0);
                const int n = n0 + wn * WN + nt * 8 + c + (e & 1);
                float v = acc[mt][nt][e] * scale;
                if (mode == 1)      v = gelu_f(v);
                else if (mode == 2) v = fabsf(gelu_f(v));
                else if (mode == 3) v = fabsf(aux[n]) * gelu_f(v);
                if (causal == 1 && n > m) v = 0.f;
                const size_t o = (size_t)m * ldc + n;
                if (Cf)  Cf[o] = v;
                if (C16) C16[o] = __float2half_rn(v);
            }
        }
    }
}

// ---------------- hs: fp32 -> bf16 hi/lo + fp16 ----------------
__global__ void split_hs_kernel(const float* __restrict__ x, bf16* __restrict__ hi,
                                bf16* __restrict__ lo, fp16* __restrict__ h16, int n)
{
    int i = blockIdx.x * blockDim.x + threadIdx.x;
    if (i >= n) return;
    float v = x[i];
    bf16 h = __float2bfloat16(v);
    hi[i] = h;
    lo[i] = __float2bfloat16(v - __bfloat162float(h));
    h16[i] = __float2half_rn(v);
}

// ---------------- split+transpose fp32 -> bf16 hi/lo (for wq, wk) ----------------
__global__ void splitT_kernel(const float* __restrict__ in, bf16* __restrict__ oh,
                              bf16* __restrict__ ol, int R, int ldin,
                              long long sIn, long long sOut)
{
    in += (long long)blockIdx.z * sIn;
    oh += (long long)blockIdx.z * sOut;
    ol += (long long)blockIdx.z * sOut;
    __shared__ float t[32][33];
    int r0 = blockIdx.y * 32, c0 = blockIdx.x * 32;
    int tx = threadIdx.x, ty = threadIdx.y;  // (32, 8)
#pragma unroll
    for (int i = 0; i < 4; i++)
        t[ty + 8 * i][tx] = in[(size_t)(r0 + ty + 8 * i) * ldin + c0 + tx];
    __syncthreads();
#pragma unroll
    for (int i = 0; i < 4; i++) {
        int oc = ty + 8 * i;
        float v = t[tx][oc];
        size_t o = (size_t)(c0 + oc) * R + r0 + tx;
        bf16 h = __float2bfloat16(v);
        oh[o] = h;
        ol[o] = __float2bfloat16(v - __bfloat162float(h));
    }
}

// ---------------- transpose fp32 -> fp16 single ----------------
__global__ void splitT16_kernel(const float* __restrict__ in, fp16* __restrict__ o16,
                                int R, int ldin, long long sIn, long long sOut)
{
    in += (long long)blockIdx.z * sIn;
    o16 += (long long)blockIdx.z * sOut;
    __shared__ float t[32][33];
    int r0 = blockIdx.y * 32, c0 = blockIdx.x * 32;
    int tx = threadIdx.x, ty = threadIdx.y;
#pragma unroll
    for (int i = 0; i < 4; i++)
        t[ty + 8 * i][tx] = in[(size_t)(r0 + ty + 8 * i) * ldin + c0 + tx];
    __syncthreads();
#pragma unroll
    for (int i = 0; i < 4; i++) {
        int oc = ty + 8 * i;
        o16[(size_t)(c0 + oc) * R + r0 + tx] = __float2half_rn(t[tx][oc]);
    }
}

// ---------------- rotary: fp32 q,k -> bf16 hi/lo + fp16 ----------------
__global__ void rotary_split_kernel(const float* __restrict__ q, const float* __restrict__ k,
                                    bf16* __restrict__ qh, bf16* __restrict__ ql,
                                    bf16* __restrict__ kh, bf16* __restrict__ kl,
                                    fp16* __restrict__ q16, fp16* __restrict__ k16)
{
    int idx = blockIdx.x * blockDim.x + threadIdx.x;
    if (idx >= S * H * 64) return;
    int i = idx & 63;
    int h = (idx >> 6) & 31;
    int s = idx >> 11;
    float inv = expf(-9.210340371976184f * (float)i / 64.0f);
    float ang = (float)s * inv;
    float sn, c;
    sincosf(ang, &sn, &c);
    long long base = (long long)s * D + h * HD;
    {
        float x1 = q[base + i], x2 = q[base + 64 + i];
        float r1 = x1 * c - x2 * sn;
        float r2 = x2 * c + x1 * sn;
        bf16 h1 = __float2bfloat16(r1); qh[base + i] = h1;      ql[base + i] = __float2bfloat16(r1 - __bfloat162float(h1));
        bf16 h2 = __float2bfloat16(r2); qh[base + 64 + i] = h2; ql[base + 64 + i] = __float2bfloat16(r2 - __bfloat162float(h2));
        q16[base + i] = __float2half_rn(r1);
        q16[base + 64 + i] = __float2half_rn(r2);
    }
    {
        float x1 = k[base + i], x2 = k[base + 64 + i];
        float r1 = x1 * c - x2 * sn;
        float r2 = x2 * c + x1 * sn;
        bf16 h1 = __float2bfloat16(r1); kh[base + i] = h1;      kl[base + i] = __float2bfloat16(r1 - __bfloat162float(h1));
        bf16 h2 = __float2bfloat16(r2); kh[base + 64 + i] = h2; kl[base + 64 + i] = __float2bfloat16(r2 - __bfloat162float(h2));
        k16[base + i] = __float2half_rn(r1);
        k16[base + 64 + i] = __float2half_rn(r2);
    }
}

// ---------------- k_ker interaction: kker = |kkA + (kkA @ ik) * scD2| ----------------
__global__ __launch_bounds__(256)
void interact_kernel(const float* __restrict__ kkA, const float* __restrict__ ik,
                     const float* __restrict__ sc2, float* __restrict__ kker)
{
    int h = blockIdx.y;
    int s0 = blockIdx.x * 64;
    int tid = threadIdx.x;
    __shared__ float sIK[KD][KD];
    __shared__ float sA[64][KD + 1];
    for (int idx = tid; idx < KD * KD; idx += 256)
        sIK[idx >> 6][idx & 63] = ik[(size_t)h * KD * KD + idx];
    for (int idx = tid; idx < 64 * KD; idx += 256) {
        int r = idx >> 6, e = idx & 63;
        sA[r][e] = kkA[((size_t)h * S + s0 + r) * KD + e];
    }
    __syncthreads();
    int r = tid >> 2;
    int f0 = (tid & 3) * 16;
#pragma unroll
    for (int ff = 0; ff < 16; ff++) {
        int f = f0 + ff;
        float sum = 0.f;
#pragma unroll
        for (int e = 0; e < KD; e++) sum += sA[r][e] * sIK[e][f];
        float val = sA[r][f] + sum * sc2[h * KD + f];
        kker[((size_t)h * S + s0 + r) * KD + f] = fabsf(val);
    }
}

// ---------------- fused causal softmax: fp32 logits -> fp16 hi/lo probs ----------------
__global__ void softmax_kernel(const float* __restrict__ logits,
                               fp16* __restrict__ ph, fp16* __restrict__ pl)
{
    int q = blockIdx.x;
    int h = blockIdx.y;
    const float* row = logits + ((size_t)h * S + q) * S;
    fp16* rh = ph + ((size_t)h * S + q) * S;
    fp16* rl = pl + ((size_t)h * S + q) * S;
    int len = q + 1;
    int tid = threadIdx.x;
    __shared__ float red[128];

    float vals[16];
    float m = -FLT_MAX;
#pragma unroll
    for (int i = 0; i < 16; i++) {
        int k = tid + i * 128;
        vals[i] = (k < len) ? row[k] : -FLT_MAX;
        m = fmaxf(m, vals[i]);
    }
    red[tid] = m; __syncthreads();
    for (int off = 64; off > 0; off >>= 1) {
        if (tid < off) red[tid] = fmaxf(red[tid], red[tid + off]);
        __syncthreads();
    }
    m = red[0]; __syncthreads();

    float sum = 0.f;
#pragma unroll
    for (int i = 0; i < 16; i++) {
        float e = __expf(vals[i] - m);
        vals[i] = e;
        sum += e;
    }
    red[tid] = sum; __syncthreads();
    for (int off = 64; off > 0; off >>= 1) {
        if (tid < off) red[tid] += red[tid + off];
        __syncthreads();
    }
    float inv = 1.0f / red[0];
#pragma unroll
    for (int i = 0; i < 16; i++) {
        int k = tid + i * 128;
        if (k < len) {
            float p = vals[i] * inv;
            fp16 hv = __float2half_rn(p);
            rh[k] = hv;
            rl[k] = __float2half_rn(p - __half2float(hv));
        }
    }
}

// ---------------- column sums of probs (upper triangle is exactly 0) ----------------
__global__ void scores_kernel(const fp16* __restrict__ ph, const fp16* __restrict__ pl,
                              float* __restrict__ scores)
{
    int h = blockIdx.y;
    int k = blockIdx.x * 256 + threadIdx.x;
    const fp16* p1 = ph + (size_t)h * S * S + k;
    const fp16* p2 = pl + (size_t)h * S * S + k;
    float s = 0.f;
    for (int q = 0; q < S; q++)
        s += __half2float(p1[(size_t)q * S]) + __half2float(p2[(size_t)q * S]);
    scores[h * S + k] = s;
}

// ---------------- top-HEAVY selection -> elim mask ----------------
__global__ __launch_bounds__(256)
void topk_kernel(const float* __restrict__ scores, float* __restrict__ elim)
{
    int h = blockIdx.x;
    int tid = threadIdx.x;
    __shared__ float sv[NSEL];
    __shared__ float rv[256];
    __shared__ int   ri[256];
    for (int j = tid; j < NSEL; j += 256) sv[j] = scores[h * S + j];
    for (int s = tid; s < S; s += 256) elim[h * S + s] = (s <= NSEL) ? 1.f : 0.f;
    __syncthreads();
    for (int iter = 0; iter < HEAVY; iter++) {
        float best = -1.f; int bi = 0x7fffffff;
        for (int j = tid; j < NSEL; j += 256) {
            float vv = sv[j];
            if (vv > best) { best = vv; bi = j; }
        }
        rv[tid] = best; ri[tid] = bi; __syncthreads();
        for (int off = 128; off > 0; off >>= 1) {
            if (tid < off) {
                float ov = rv[tid + off]; int oi = ri[tid + off];
                if (ov > rv[tid] || (ov == rv[tid] && oi < ri[tid])) { rv[tid] = ov; ri[tid] = oi; }
            }
            __syncthreads();
        }
        if (tid == 0) { int b = ri[0]; elim[h * S + b] = 0.f; sv[b] = -2.f; }
        __syncthreads();
    }
}

// ---------------- H_new / z_new ----------------
__global__ __launch_bounds__(256)
void hnew_kernel(const float* __restrict__ kker, const float* __restrict__ v,
                 const float* __restrict__ elim,
                 float* __restrict__ Hout, float* __restrict__ zout)
{
    int h = blockIdx.x;
    int tid = threadIdx.x;
    __shared__ float skk[32][KD];
    __shared__ float sv[32][HD];
    int dg = tid & 15;
    int eg = tid >> 4;
    float acc[4][8];
#pragma unroll
    for (int e = 0; e < 4; e++)
#pragma unroll
        for (int d = 0; d < 8; d++) acc[e][d] = 0.f;
    float zacc = 0.f;

    const float* kkh = kker + (size_t)h * S * KD;
    const float* vh  = v + h * HD;
    for (int s0 = 0; s0 < S; s0 += 32) {
        for (int idx = tid; idx < 32 * KD; idx += 256) {
            int si = idx >> 6; int e = idx & 63;
            skk[si][e] = kkh[(size_t)(s0 + si) * KD + e] * elim[h * S + s0 + si];
        }
        for (int idx = tid; idx < 32 * HD; idx += 256) {
            int si = idx >> 7; int d = idx & 127;
            sv[si][d] = vh[(size_t)(s0 + si) * D + d];
        }
        __syncthreads();
        if (tid < KD) {
#pragma unroll
            for (int si = 0; si < 32; si++) zacc += skk[si][tid];
        }
#pragma unroll 4
        for (int si = 0; si < 32; si++) {
            float ke[4], vd[8];
#pragma unroll
            for (int e = 0; e < 4; e++) ke[e] = skk[si][eg * 4 + e];
#pragma unroll
            for (int d = 0; d < 8; d++) vd[d] = sv[si][dg * 8 + d];
#pragma unroll
            for (int e = 0; e < 4; e++)
#pragma unroll
                for (int d = 0; d < 8; d++)
                    acc[e][d] += ke[e] * vd[d];
        }
        __syncthreads();
    }
#pragma unroll
    for (int e = 0; e < 4; e++)
#pragma unroll
        for (int d = 0; d < 8; d++)
            Hout[(size_t)h * KD * HD + (eg * 4 + e) * HD + dg * 8 + d] = acc[e][d];
    if (tid < KD) zout[h * KD + tid] = zacc;
}

// ---------------- host side ----------------
template <typename T>
static float* sym_f(T& sym) { void* p = nullptr; cudaGetSymbolAddress(&p, sym); return (float*)p; }
template <typename T>
static bf16* sym_b(T& sym) { void* p = nullptr; cudaGetSymbolAddress(&p, sym); return (bf16*)p; }
template <typename T>
static fp16* sym_h(T& sym) { void* p = nullptr; cudaGetSymbolAddress(&p, sym); return (fp16*)p; }

template <int NT, int NA, int NB, bool BF>
static void launch_gemm(const void* A0, const void* A1, const void* B0, const void* B1,
                        float* Cf, fp16* C16,
                        int M, int N, int K, int lda, int ldb, int ldc,
                        long long sA, long long sB, long long sC, int batch,
                        float scale, int mode, int causal,
                        const float* aux = nullptr, long long sAux = 0)
{
    constexpr int STAGE = (NA * 128 + NB * NT) * PITCH;
    cudaFuncSetAttribute(hm_gemm<NT, NA, NB, BF>,
                         cudaFuncAttributeMaxDynamicSharedMemorySize, 2 * STAGE);
    dim3 grid(N / NT, M / 128, batch);
    hm_gemm<NT, NA, NB, BF><<<grid, 256, 2 * STAGE>>>(
        (const uint16_t*)A0, (const uint16_t*)A1, (const uint16_t*)B0, (const uint16_t*)B1,
        Cf, C16, K, lda, ldb, ldc, sA, sB, sC, scale, mode, causal, aux, sAux);
}

extern "C" void kernel_launch(void* const* d_in, const int* in_sizes, int n_in,
                              void* d_out, int out_size)
{
    const float* hs   = (const float*)d_in[0];
    const float* wq   = (const float*)d_in[1];
    const float* wk   = (const float*)d_in[2];
    const float* wv   = (const float*)d_in[3];
    const float* wo   = (const float*)d_in[4];
    const float* kq1  = (const float*)d_in[5];
    const float* kq2  = (const float*)d_in[6];
    const float* kk1  = (const float*)d_in[7];
    const float* kk2  = (const float*)d_in[8];
    const float* scD  = (const float*)d_in[9];
    const float* ik   = (const float*)d_in[10];
    const float* scD2 = (const float*)d_in[11];

    float* out   = (float*)d_out;
    float* outO  = out;
    float* outH  = out + (size_t)S * D;
    float* outZ  = outH + (size_t)H * KD * HD;
    float* outQk = outZ + (size_t)H * KD;

    float* q = sym_f(g_q);  float* k = sym_f(g_k);  float* v = sym_f(g_v);
    bf16 *hsh = sym_b(g_hsh), *hsl = sym_b(g_hsl);
    fp16 *hs16 = sym_h(g_hs16);
    bf16 *qh = sym_b(g_qh), *ql = sym_b(g_ql), *kh = sym_b(g_kh), *kl = sym_b(g_kl);
    fp16 *q16 = sym_h(g_q16), *k16 = sym_h(g_k16);
    fp16 *vt16 = sym_h(g_vt16);
    bf16 *wqth = sym_b(g_wqth), *wqtl = sym_b(g_wqtl);
    bf16 *wkth = sym_b(g_wkth), *wktl = sym_b(g_wktl);
    fp16 *wvt16 = sym_h(g_wvt16), *wot16 = sym_h(g_wot16);
    fp16 *kq1t = sym_h(g_kq1t), *kk1t = sym_h(g_kk1t);
    fp16 *kq2t = sym_h(g_kq2t), *kk2t = sym_h(g_kk2t);
    fp16 *t116 = sym_h(g_t116);
    fp16 *ph = sym_h(g_ph), *pl = sym_h(g_pl);
    fp16 *ctx16 = sym_h(g_ctx16);
    float* kkA = sym_f(g_kkA);
    float* kker = sym_f(g_kker);
    float* logits = sym_f(g_logits);
    float* scores = sym_f(g_scores);
    float* elim = sym_f(g_elim);

    // ---- 0) operand prep ----
    split_hs_kernel<<<(S * D + 255) / 256, 256>>>(hs, hsh, hsl, hs16, S * D);
    {
        dim3 g(D / 32, D / 32, 1), b(32, 8);
        splitT_kernel<<<g, b>>>(wq, wqth, wqtl, D, D, 0, 0);
        splitT_kernel<<<g, b>>>(wk, wkth, wktl, D, D, 0, 0);
        splitT16_kernel<<<g, b>>>(wv, wvt16, D, D, 0, 0);
        splitT16_kernel<<<g, b>>>(wo, wot16, D, D, 0, 0);
    }
    {
        dim3 g(KH / 32, HD / 32, H), b(32, 8);
        splitT16_kernel<<<g, b>>>(kq1, kq1t, HD, KH, (long long)HD * KH, (long long)KH * HD);
        splitT16_kernel<<<g, b>>>(kk1, kk1t, HD, KH, (long long)HD * KH, (long long)KH * HD);
    }
    {
        dim3 g(KD / 32, KH / 32, H), b(32, 8);
        splitT16_kernel<<<g, b>>>(kq2, kq2t, KH, KD, (long long)KH * KD, (long long)KD * KH);
        splitT16_kernel<<<g, b>>>(kk2, kk2t, KH, KD, (long long)KH * KD, (long long)KD * KH);
    }

    // ---- 1) QKV projections ----
    launch_gemm<128, 2, 2, true>(hsh, hsl, wqth, wqtl, q, nullptr,
                                 S, D, D, D, D, D, 0, 0, 0, 1, 1.f, 0, 0);
    launch_gemm<128, 2, 2, true>(hsh, hsl, wkth, wktl, k, nullptr,
                                 S, D, D, D, D, D, 0, 0, 0, 1, 1.f, 0, 0);
    launch_gemm<128, 1, 1, false>(hs16, nullptr, wvt16, nullptr, v, nullptr,
                                  S, D, D, D, D, D, 0, 0, 0, 1, 1.f, 0, 0);

    // ---- 2) rotary ----
    rotary_split_kernel<<<(S * H * 64 + 255) / 256, 256>>>(q, k, qh, ql, kh, kl, q16, k16);

    // ---- 3) v^T fp16 per head ----
    {
        dim3 g(HD / 32, S / 32, H), b(32, 8);
        splitT16_kernel<<<g, b>>>(v, vt16, S, D, (long long)HD, (long long)HD * S);
    }

    // ---- 4) q_ker path (fp16 single) ----
    launch_gemm<128, 1, 1, false>(q16, nullptr, kq1t, nullptr, nullptr, t116,
                                  S, KH, HD, D, HD, KH,
                                  HD, (long long)KH * HD, (long long)S * KH, H, 1.f, 1, 0);
    launch_gemm<64, 1, 1, false>(t116, nullptr, kq2t, nullptr, outQk, nullptr,
                                 S, KD, KH, KH, KH, KD,
                                 (long long)S * KH, (long long)KD * KH, (long long)S * KD, H, 1.f, 2, 0);

    // ---- 5) k_ker path (fp16 single) ----
    launch_gemm<128, 1, 1, false>(k16, nullptr, kk1t, nullptr, nullptr, t116,
                                  S, KH, HD, D, HD, KH,
                                  HD, (long long)KH * HD, (long long)S * KH, H, 1.f, 1, 0);
    launch_gemm<64, 1, 1, false>(t116, nullptr, kk2t, nullptr, kkA, nullptr,
                                 S, KD, KH, KH, KH, KD,
                                 (long long)S * KH, (long long)KD * KH, (long long)S * KD, H, 1.f, 3, 0, scD, KD);

    // ---- 6) interaction -> kker ----
    {
        dim3 grid(S / 64, H);
        interact_kernel<<<grid, 256>>>(kkA, ik, scD2, kker);
    }

    // ---- 7) causal logits (bf16 3-pass: precision for top-k path) ----
    launch_gemm<128, 2, 2, true>(qh, ql, kh, kl, logits, nullptr,
                                 S, S, HD, D, D, S,
                                 HD, HD, (long long)S * S, H, 0.08838834764831843f, 0, 1);

    // ---- 8) fused softmax -> fp16 hi/lo probs ----
    {
        dim3 grid(S, H);
        softmax_kernel<<<grid, 128>>>(logits, ph, pl);
    }

    // ---- 9) scores / topk / hnew ----
    {
        dim3 grid(S / 256, H);
        scores_kernel<<<grid, 256>>>(ph, pl, scores);
    }
    topk_kernel<<<H, 256>>>(scores, elim);
    hnew_kernel<<<H, 256>>>(kker, v, elim, outH, outZ);

    // ---- 10) ctx = (ph+pl) @ v16  (2-pass, causal K-limit) ----
    launch_gemm<128, 2, 1, false>(ph, pl, vt16, nullptr, nullptr, ctx16,
                                  S, HD, S, S, S, D,
                                  (long long)S * S, (long long)HD * S, (long long)HD, H, 1.f, 0, 2);

    // ---- 11) out = ctx @ wo (fp16 single) ----
    launch_gemm<128, 1, 1, false>(ctx16, nullptr, wot16, nullptr, outO, nullptr,
                                  S, D, D, D, D, D, 0, 0, 0, 1, 1.f, 0, 0);
}

// round 11
// speedup vs baseline: 3.2824x; 1.1769x over previous
#include <cuda_runtime.h>
#include <cuda_bf16.h>
#include <cuda_fp16.h>
#include <math.h>
#include <float.h>
#include <stdint.h>

#define S 2048
#define D 4096
#define H 32
#define HD 128
#define KH 128
#define KD 64
#define HEAVY 256
#define RECENT 256
#define NSEL (S - RECENT)   // 1792

typedef __nv_bfloat16 bf16;
typedef __half fp16;

// ---------------- scratch (device globals; zero-initialized at load) ----------------
__device__ float g_q[(size_t)S * D];
__device__ float g_k[(size_t)S * D];
__device__ float g_v[(size_t)S * D];
__device__ __align__(16) bf16 g_hsh[(size_t)S * D];
__device__ __align__(16) bf16 g_hsl[(size_t)S * D];
__device__ __align__(16) fp16 g_hs16[(size_t)S * D];
__device__ __align__(16) bf16 g_qh[(size_t)S * D];
__device__ __align__(16) bf16 g_ql[(size_t)S * D];
__device__ __align__(16) bf16 g_kh[(size_t)S * D];
__device__ __align__(16) bf16 g_kl[(size_t)S * D];
__device__ __align__(16) fp16 g_q16[(size_t)S * D];
__device__ __align__(16) fp16 g_k16[(size_t)S * D];
__device__ __align__(16) fp16 g_vt16[(size_t)H * HD * S];
__device__ __align__(16) bf16 g_wqth[(size_t)D * D];
__device__ __align__(16) bf16 g_wqtl[(size_t)D * D];
__device__ __align__(16) bf16 g_wkth[(size_t)D * D];
__device__ __align__(16) bf16 g_wktl[(size_t)D * D];
__device__ __align__(16) fp16 g_wvt16[(size_t)D * D];
__device__ __align__(16) fp16 g_wot16[(size_t)D * D];
__device__ __align__(16) fp16 g_kq1t[(size_t)H * KH * HD];
__device__ __align__(16) fp16 g_kk1t[(size_t)H * KH * HD];
__device__ __align__(16) fp16 g_kq2t[(size_t)H * KD * KH];
__device__ __align__(16) fp16 g_kk2t[(size_t)H * KD * KH];
__device__ __align__(16) fp16 g_t116[(size_t)H * S * KH];
__device__ float g_kkA[(size_t)H * S * KD];
__device__ float g_kker[(size_t)H * S * KD];
__device__ float g_logits[(size_t)H * S * S];   // 512 MB
__device__ __align__(16) fp16 g_ph[(size_t)H * S * S];        // 256 MB
__device__ __align__(16) fp16 g_ctx16[(size_t)S * D];
__device__ float g_hpart[(size_t)H * 8 * KD * HD];
__device__ float g_zpart[(size_t)H * 8 * KD];
__device__ float g_scores[H * S];
__device__ float g_elim[H * S];

__device__ __forceinline__ float gelu_f(float x) {
    return 0.5f * x * (1.0f + erff(x * 0.7071067811865476f));
}

// FMA-pipe exp: exp(x) = 2^n * exp(f*ln2), |f| <= 0.5, degree-5 Taylor (rel err ~2.4e-6)
__device__ __forceinline__ float fast_exp(float x) {
    float y = x * 1.4426950408889634f;
    float n = rintf(y);
    float t = (y - n) * 0.6931471805599453f;
    float p = 8.3333333e-3f;
    p = fmaf(p, t, 4.1666667e-2f);
    p = fmaf(p, t, 1.6666667e-1f);
    p = fmaf(p, t, 0.5f);
    p = fmaf(p, t, 1.0f);
    p = fmaf(p, t, 1.0f);
    int e = (int)n;
    e = e < -126 ? -126 : (e > 126 ? 126 : e);
    return p * __int_as_float((e + 127) << 23);
}

// ============================ PTX helpers ============================
__device__ __forceinline__ uint32_t smem_u32(const void* p) {
    uint32_t a;
    asm("{ .reg .u64 t; cvta.to.shared.u64 t, %1; cvt.u32.u64 %0, t; }" : "=r"(a) : "l"(p));
    return a;
}
__device__ __forceinline__ void cp16(uint32_t dst, const void* src) {
    asm volatile("cp.async.cg.shared.global [%0], [%1], 16;" :: "r"(dst), "l"(src));
}
#define CP_COMMIT() asm volatile("cp.async.commit_group;" ::: "memory")
#define CP_WAIT(n)  asm volatile("cp.async.wait_group %0;" :: "n"(n) : "memory")

#define LDSM4(r, addr) \
    asm volatile("ldmatrix.sync.aligned.m8n8.x4.shared.b16 {%0,%1,%2,%3}, [%4];" \
        : "=r"((r)[0]), "=r"((r)[1]), "=r"((r)[2]), "=r"((r)[3]) : "r"(addr))

#define MMA_BF(d, a, b) \
    asm volatile("mma.sync.aligned.m16n8k16.row.col.f32.bf16.bf16.f32 " \
        "{%0,%1,%2,%3}, {%4,%5,%6,%7}, {%8,%9}, {%0,%1,%2,%3};" \
        : "+f"((d)[0]), "+f"((d)[1]), "+f"((d)[2]), "+f"((d)[3]) \
        : "r"((a)[0]), "r"((a)[1]), "r"((a)[2]), "r"((a)[3]), "r"((b)[0]), "r"((b)[1]))

#define MMA_FP(d, a, b) \
    asm volatile("mma.sync.aligned.m16n8k16.row.col.f32.f16.f16.f32 " \
        "{%0,%1,%2,%3}, {%4,%5,%6,%7}, {%8,%9}, {%0,%1,%2,%3};" \
        : "+f"((d)[0]), "+f"((d)[1]), "+f"((d)[2]), "+f"((d)[3]) \
        : "r"((a)[0]), "r"((a)[1]), "r"((a)[2]), "r"((a)[3]), "r"((b)[0]), "r"((b)[1]))

// ============================ HMMA multi-pass GEMM ============================
// C[m,n] = epi( scale * sum_k (A0 [+A1])[m,k] * (B0 [+B1])[n,k] )  (B N-major)
// passes: (a0,b0); +(a0,b1) if NB==2; +(a1,b0) if NA==2.   (lo*lo dropped)
// modes: 0 none, 1 gelu, 2 abs(gelu), 3 |aux[n]|*gelu
// causal: 0 none; 1 logits (skip n0>m0 tiles, zero n>m); 2 K limited to m0+128.
#define PITCH 144          // 128 data bytes + 16 pad per smem row
#define BKE 64             // k elements per stage

template <int NT, int NA, int NB, bool BF>
__global__ __launch_bounds__(256)
void hm_gemm(const uint16_t* __restrict__ A0, const uint16_t* __restrict__ A1,
             const uint16_t* __restrict__ B0, const uint16_t* __restrict__ B1,
             float* __restrict__ Cf, fp16* __restrict__ C16,
             int K, int lda, int ldb, int ldc,
             long long sA, long long sB, long long sC,
             float scale, int mode, int causal,
             const float* __restrict__ aux, long long sAux)
{
    constexpr int WN = NT / 2;         // warp n-extent (4x2 warp grid)
    constexpr int NT8 = WN / 8;        // n8 tiles per warp
    constexpr int ASZ = 128 * PITCH;
    constexpr int BSZ = NT * PITCH;
    constexpr int STAGE = NA * ASZ + NB * BSZ;
    extern __shared__ char smem[];

    const int tid = threadIdx.x;
    const int lane = tid & 31, wrp = tid >> 5;
    const int wm = wrp >> 1, wn = wrp & 1;
    const int m0 = blockIdx.y * 128;
    const int n0 = blockIdx.x * NT;
    if (causal == 1 && n0 > m0) return;

    const long long z = blockIdx.z;
    const uint16_t* Aop[2] = { A0 + z * sA, A1 ? A1 + z * sA : nullptr };
    const uint16_t* Bop[2] = { B0 + z * sB, B1 ? B1 + z * sB : nullptr };
    if (Cf) Cf += z * sC;
    if (C16) C16 += z * sC;
    if (aux) aux += z * sAux;

    const uint32_t sbase = smem_u32(smem);

    float acc[2][NT8][4];
#pragma unroll
    for (int i = 0; i < 2; i++)
#pragma unroll
        for (int j = 0; j < NT8; j++)
#pragma unroll
            for (int t = 0; t < 4; t++) acc[i][j][t] = 0.f;

    const int Keff = (causal == 2) ? (m0 + 128) : K;
    const int nch = Keff / BKE;

    auto load_stage = [&](int kc, int st) {
        const int k0 = kc * BKE;
        const uint32_t base = sbase + st * STAGE;
#pragma unroll
        for (int a = 0; a < NA; a++) {
            const uint32_t ab = base + a * ASZ;
#pragma unroll
            for (int it = 0; it < 4; it++) {
                int idx = tid + it * 256;              // 0..1023
                int r = idx >> 3, cb = (idx & 7) * 16;
                cp16(ab + r * PITCH + cb, Aop[a] + (size_t)(m0 + r) * lda + k0 + (cb >> 1));
            }
        }
#pragma unroll
        for (int b = 0; b < NB; b++) {
            const uint32_t bb = base + NA * ASZ + b * BSZ;
#pragma unroll
            for (int it = 0; it < NT / 32; it++) {
                int idx = tid + it * 256;
                int r = idx >> 3, cb = (idx & 7) * 16;
                cp16(bb + r * PITCH + cb, Bop[b] + (size_t)(n0 + r) * ldb + k0 + (cb >> 1));
            }
        }
        CP_COMMIT();
    };

    load_stage(0, 0);
    for (int i = 0; i < nch; i++) {
        const int st = i & 1;
        if (i + 1 < nch) { load_stage(i + 1, 1 - st); CP_WAIT(1); }
        else             { CP_WAIT(0); }
        __syncthreads();

        const uint32_t base = sbase + st * STAGE;

#pragma unroll
        for (int ks = 0; ks < 4; ks++) {
            const uint32_t ksoff = ks * 32;           // bytes (16 elems)
            uint32_t af[NA][2][4];
#pragma unroll
            for (int a = 0; a < NA; a++) {
#pragma unroll
                for (int mt = 0; mt < 2; mt++) {
                    int row = wm * 32 + mt * 16 + (lane & 15);
                    uint32_t col = ksoff + ((lane & 16) ? 16 : 0);
                    LDSM4(af[a][mt], base + a * ASZ + row * PITCH + col);
                }
            }
            uint32_t bfr[NB][NT8][2];
#pragma unroll
            for (int b = 0; b < NB; b++) {
#pragma unroll
                for (int jp = 0; jp < NT8 / 2; jp++) {
                    int row = wn * WN + jp * 16 + (lane & 7) + ((lane & 16) >> 1);
                    uint32_t col = ksoff + ((lane & 8) ? 16 : 0);
                    uint32_t r4[4];
                    LDSM4(r4, base + NA * ASZ + b * BSZ + row * PITCH + col);
                    bfr[b][2 * jp][0] = r4[0]; bfr[b][2 * jp][1] = r4[1];
                    bfr[b][2 * jp + 1][0] = r4[2]; bfr[b][2 * jp + 1][1] = r4[3];
                }
            }
            // pass 1: a0*b0
#pragma unroll
            for (int mt = 0; mt < 2; mt++)
#pragma unroll
                for (int nt = 0; nt < NT8; nt++) {
                    if (BF) { MMA_BF(acc[mt][nt], af[0][mt], bfr[0][nt]); }
                    else    { MMA_FP(acc[mt][nt], af[0][mt], bfr[0][nt]); }
                }
            // pass 2: a0*b1
            if (NB == 2) {
#pragma unroll
                for (int mt = 0; mt < 2; mt++)
#pragma unroll
                    for (int nt = 0; nt < NT8; nt++) {
                        if (BF) { MMA_BF(acc[mt][nt], af[0][mt], bfr[NB - 1][nt]); }
                        else    { MMA_FP(acc[mt][nt], af[0][mt], bfr[NB - 1][nt]); }
                    }
            }
            // pass 3: a1*b0
            if (NA == 2) {
#pragma unroll
                for (int mt = 0; mt < 2; mt++)
#pragma unroll
                    for (int nt = 0; nt < NT8; nt++) {
                        if (BF) { MMA_BF(acc[mt][nt], af[NA - 1][mt], bfr[0][nt]); }
                        else    { MMA_FP(acc[mt][nt], af[NA - 1][mt], bfr[0][nt]); }
                    }
            }
        }
        __syncthreads();
    }

    // ---- epilogue ----
    const int r = lane >> 2, c = (lane & 3) * 2;
#pragma unroll
    for (int mt = 0; mt < 2; mt++) {
#pragma unroll
        for (int nt = 0; nt < NT8; nt++) {
#pragma unroll
            for (int e = 0; e < 4; e++) {
                const int m = m0 + wm * 32 + mt * 16 + r + ((e >> 1) ? 8 : 0);
                const int n = n0 + wn * WN + nt * 8 + c + (e & 1);
                float v = acc[mt][nt][e] * scale;
                if (mode == 1)      v = gelu_f(v);
                else if (mode == 2) v = fabsf(gelu_f(v));
                else if (mode == 3) v = fabsf(aux[n]) * gelu_f(v);
                if (causal == 1 && n > m) v = 0.f;
                const size_t o = (size_t)m * ldc + n;
                if (Cf)  Cf[o] = v;
                if (C16) C16[o] = __float2half_rn(v);
            }
        }
    }
}

// ---------------- hs: fp32 -> bf16 hi/lo + fp16 ----------------
__global__ void split_hs_kernel(const float* __restrict__ x, bf16* __restrict__ hi,
                                bf16* __restrict__ lo, fp16* __restrict__ h16, int n)
{
    int i = blockIdx.x * blockDim.x + threadIdx.x;
    if (i >= n) return;
    float v = x[i];
    bf16 h = __float2bfloat16(v);
    hi[i] = h;
    lo[i] = __float2bfloat16(v - __bfloat162float(h));
    h16[i] = __float2half_rn(v);
}

// ---------------- split+transpose fp32 -> bf16 hi/lo (for wq, wk) ----------------
__global__ void splitT_kernel(const float* __restrict__ in, bf16* __restrict__ oh,
                              bf16* __restrict__ ol, int R, int ldin,
                              long long sIn, long long sOut)
{
    in += (long long)blockIdx.z * sIn;
    oh += (long long)blockIdx.z * sOut;
    ol += (long long)blockIdx.z * sOut;
    __shared__ float t[32][33];
    int r0 = blockIdx.y * 32, c0 = blockIdx.x * 32;
    int tx = threadIdx.x, ty = threadIdx.y;  // (32, 8)
#pragma unroll
    for (int i = 0; i < 4; i++)
        t[ty + 8 * i][tx] = in[(size_t)(r0 + ty + 8 * i) * ldin + c0 + tx];
    __syncthreads();
#pragma unroll
    for (int i = 0; i < 4; i++) {
        int oc = ty + 8 * i;
        float v = t[tx][oc];
        size_t o = (size_t)(c0 + oc) * R + r0 + tx;
        bf16 h = __float2bfloat16(v);
        oh[o] = h;
        ol[o] = __float2bfloat16(v - __bfloat162float(h));
    }
}

// ---------------- transpose fp32 -> fp16 single ----------------
__global__ void splitT16_kernel(const float* __restrict__ in, fp16* __restrict__ o16,
                                int R, int ldin, long long sIn, long long sOut)
{
    in += (long long)blockIdx.z * sIn;
    o16 += (long long)blockIdx.z * sOut;
    __shared__ float t[32][33];
    int r0 = blockIdx.y * 32, c0 = blockIdx.x * 32;
    int tx = threadIdx.x, ty = threadIdx.y;
#pragma unroll
    for (int i = 0; i < 4; i++)
        t[ty + 8 * i][tx] = in[(size_t)(r0 + ty + 8 * i) * ldin + c0 + tx];
    __syncthreads();
#pragma unroll
    for (int i = 0; i < 4; i++) {
        int oc = ty + 8 * i;
        o16[(size_t)(c0 + oc) * R + r0 + tx] = __float2half_rn(t[tx][oc]);
    }
}

// ---------------- rotary: fp32 q,k -> bf16 hi/lo + fp16 ----------------
__global__ void rotary_split_kernel(const float* __restrict__ q, const float* __restrict__ k,
                                    bf16* __restrict__ qh, bf16* __restrict__ ql,
                                    bf16* __restrict__ kh, bf16* __restrict__ kl,
                                    fp16* __restrict__ q16, fp16* __restrict__ k16)
{
    int idx = blockIdx.x * blockDim.x + threadIdx.x;
    if (idx >= S * H * 64) return;
    int i = idx & 63;
    int h = (idx >> 6) & 31;
    int s = idx >> 11;
    float inv = expf(-9.210340371976184f * (float)i / 64.0f);
    float ang = (float)s * inv;
    float sn, c;
    sincosf(ang, &sn, &c);
    long long base = (long long)s * D + h * HD;
    {
        float x1 = q[base + i], x2 = q[base + 64 + i];
        float r1 = x1 * c - x2 * sn;
        float r2 = x2 * c + x1 * sn;
        bf16 h1 = __float2bfloat16(r1); qh[base + i] = h1;      ql[base + i] = __float2bfloat16(r1 - __bfloat162float(h1));
        bf16 h2 = __float2bfloat16(r2); qh[base + 64 + i] = h2; ql[base + 64 + i] = __float2bfloat16(r2 - __bfloat162float(h2));
        q16[base + i] = __float2half_rn(r1);
        q16[base + 64 + i] = __float2half_rn(r2);
    }
    {
        float x1 = k[base + i], x2 = k[base + 64 + i];
        float r1 = x1 * c - x2 * sn;
        float r2 = x2 * c + x1 * sn;
        bf16 h1 = __float2bfloat16(r1); kh[base + i] = h1;      kl[base + i] = __float2bfloat16(r1 - __bfloat162float(h1));
        bf16 h2 = __float2bfloat16(r2); kh[base + 64 + i] = h2; kl[base + 64 + i] = __float2bfloat16(r2 - __bfloat162float(h2));
        k16[base + i] = __float2half_rn(r1);
        k16[base + 64 + i] = __float2half_rn(r2);
    }
}

// ---------------- k_ker interaction: kker = |kkA + (kkA @ ik) * scD2| ----------------
__global__ __launch_bounds__(256)
void interact_kernel(const float* __restrict__ kkA, const float* __restrict__ ik,
                     const float* __restrict__ sc2, float* __restrict__ kker)
{
    int h = blockIdx.y;
    int s0 = blockIdx.x * 64;
    int tid = threadIdx.x;
    __shared__ float sIK[KD][KD];
    __shared__ float sA[64][KD + 1];
    for (int idx = tid; idx < KD * KD; idx += 256)
        sIK[idx >> 6][idx & 63] = ik[(size_t)h * KD * KD + idx];
    for (int idx = tid; idx < 64 * KD; idx += 256) {
        int r = idx >> 6, e = idx & 63;
        sA[r][e] = kkA[((size_t)h * S + s0 + r) * KD + e];
    }
    __syncthreads();
    int r = tid >> 2;
    int f0 = (tid & 3) * 16;
#pragma unroll
    for (int ff = 0; ff < 16; ff++) {
        int f = f0 + ff;
        float sum = 0.f;
#pragma unroll
        for (int e = 0; e < KD; e++) sum += sA[r][e] * sIK[e][f];
        float val = sA[r][f] + sum * sc2[h * KD + f];
        kker[((size_t)h * S + s0 + r) * KD + f] = fabsf(val);
    }
}

// ---------------- fused causal softmax (no max shift, FMA exp): fp32 logits -> fp16 probs ----------------
__global__ void softmax_kernel(const float* __restrict__ logits, fp16* __restrict__ ph)
{
    int q = blockIdx.x;
    int h = blockIdx.y;
    const float* row = logits + ((size_t)h * S + q) * S;
    fp16* rh = ph + ((size_t)h * S + q) * S;
    int len = q + 1;
    int tid = threadIdx.x;
    __shared__ float red[128];

    float vals[16];
    float sum = 0.f;
#pragma unroll
    for (int i = 0; i < 16; i++) {
        int k = tid + i * 128;
        float e = 0.f;
        if (k < len) e = fast_exp(row[k]);
        vals[i] = e;
        sum += e;
    }
    red[tid] = sum; __syncthreads();
    for (int off = 64; off > 0; off >>= 1) {
        if (tid < off) red[tid] += red[tid + off];
        __syncthreads();
    }
    float inv = 1.0f / red[0];
#pragma unroll
    for (int i = 0; i < 16; i++) {
        int k = tid + i * 128;
        if (k < len) rh[k] = __float2half_rn(vals[i] * inv);
    }
}

// ---------------- column sums of probs (upper triangle is exactly 0) ----------------
__global__ void scores_kernel(const fp16* __restrict__ ph, float* __restrict__ scores)
{
    int h = blockIdx.y;
    int k = blockIdx.x * 256 + threadIdx.x;
    const fp16* p1 = ph + (size_t)h * S * S + k;
    float s = 0.f;
    for (int q = 0; q < S; q++)
        s += __half2float(p1[(size_t)q * S]);
    scores[h * S + k] = s;
}

// ---------------- top-HEAVY selection -> elim mask ----------------
__global__ __launch_bounds__(256)
void topk_kernel(const float* __restrict__ scores, float* __restrict__ elim)
{
    int h = blockIdx.x;
    int tid = threadIdx.x;
    __shared__ float sv[NSEL];
    __shared__ float rv[256];
    __shared__ int   ri[256];
    for (int j = tid; j < NSEL; j += 256) sv[j] = scores[h * S + j];
    for (int s = tid; s < S; s += 256) elim[h * S + s] = (s <= NSEL) ? 1.f : 0.f;
    __syncthreads();
    for (int iter = 0; iter < HEAVY; iter++) {
        float best = -1.f; int bi = 0x7fffffff;
        for (int j = tid; j < NSEL; j += 256) {
            float vv = sv[j];
            if (vv > best) { best = vv; bi = j; }
        }
        rv[tid] = best; ri[tid] = bi; __syncthreads();
        for (int off = 128; off > 0; off >>= 1) {
            if (tid < off) {
                float ov = rv[tid + off]; int oi = ri[tid + off];
                if (ov > rv[tid] || (ov == rv[tid] && oi < ri[tid])) { rv[tid] = ov; ri[tid] = oi; }
            }
            __syncthreads();
        }
        if (tid == 0) { int b = ri[0]; elim[h * S + b] = 0.f; sv[b] = -2.f; }
        __syncthreads();
    }
}

// ---------------- H_new / z_new partials over s-chunks ----------------
__global__ __launch_bounds__(256)
void hnew_part(const float* __restrict__ kker, const float* __restrict__ v,
               const float* __restrict__ elim,
               float* __restrict__ hp, float* __restrict__ zp)
{
    int h = blockIdx.x;
    int ch = blockIdx.y;   // 0..7, each 256 rows
    int tid = threadIdx.x;
    __shared__ float skk[32][KD];
    __shared__ float sv[32][HD];
    int dg = tid & 15;
    int eg = tid >> 4;
    float acc[4][8];
#pragma unroll
    for (int e = 0; e < 4; e++)
#pragma unroll
        for (int d = 0; d < 8; d++) acc[e][d] = 0.f;
    float zacc = 0.f;

    const float* kkh = kker + (size_t)h * S * KD;
    const float* vh  = v + h * HD;
    const int sBeg = ch * 256, sEnd = sBeg + 256;
    for (int s0 = sBeg; s0 < sEnd; s0 += 32) {
        for (int idx = tid; idx < 32 * KD; idx += 256) {
            int si = idx >> 6; int e = idx & 63;
            skk[si][e] = kkh[(size_t)(s0 + si) * KD + e] * elim[h * S + s0 + si];
        }
        for (int idx = tid; idx < 32 * HD; idx += 256) {
            int si = idx >> 7; int d = idx & 127;
            sv[si][d] = vh[(size_t)(s0 + si) * D + d];
        }
        __syncthreads();
        if (tid < KD) {
#pragma unroll
            for (int si = 0; si < 32; si++) zacc += skk[si][tid];
        }
#pragma unroll 4
        for (int si = 0; si < 32; si++) {
            float ke[4], vd[8];
#pragma unroll
            for (int e = 0; e < 4; e++) ke[e] = skk[si][eg * 4 + e];
#pragma unroll
            for (int d = 0; d < 8; d++) vd[d] = sv[si][dg * 8 + d];
#pragma unroll
            for (int e = 0; e < 4; e++)
#pragma unroll
                for (int d = 0; d < 8; d++)
                    acc[e][d] += ke[e] * vd[d];
        }
        __syncthreads();
    }
    float* hout = hp + ((size_t)h * 8 + ch) * KD * HD;
#pragma unroll
    for (int e = 0; e < 4; e++)
#pragma unroll
        for (int d = 0; d < 8; d++)
            hout[(eg * 4 + e) * HD + dg * 8 + d] = acc[e][d];
    if (tid < KD) zp[((size_t)h * 8 + ch) * KD + tid] = zacc;
}

__global__ void hnew_reduce(const float* __restrict__ hp, const float* __restrict__ zp,
                            float* __restrict__ Hout, float* __restrict__ zout)
{
    int i = blockIdx.x * 256 + threadIdx.x;   // over H*KD*HD
    if (i >= H * KD * HD) return;
    int h = i / (KD * HD);
    int r = i % (KD * HD);
    float s = 0.f;
#pragma unroll
    for (int c = 0; c < 8; c++) s += hp[((size_t)h * 8 + c) * KD * HD + r];
    Hout[i] = s;
    if (i < H * KD) {
        int hh = i / KD, e = i % KD;
        float z = 0.f;
#pragma unroll
        for (int c = 0; c < 8; c++) z += zp[((size_t)hh * 8 + c) * KD + e];
        zout[i] = z;
    }
}

// ---------------- host side ----------------
template <typename T>
static float* sym_f(T& sym) { void* p = nullptr; cudaGetSymbolAddress(&p, sym); return (float*)p; }
template <typename T>
static bf16* sym_b(T& sym) { void* p = nullptr; cudaGetSymbolAddress(&p, sym); return (bf16*)p; }
template <typename T>
static fp16* sym_h(T& sym) { void* p = nullptr; cudaGetSymbolAddress(&p, sym); return (fp16*)p; }

template <int NT, int NA, int NB, bool BF>
static void launch_gemm(const void* A0, const void* A1, const void* B0, const void* B1,
                        float* Cf, fp16* C16,
                        int M, int N, int K, int lda, int ldb, int ldc,
                        long long sA, long long sB, long long sC, int batch,
                        float scale, int mode, int causal,
                        const float* aux = nullptr, long long sAux = 0)
{
    constexpr int STAGE = (NA * 128 + NB * NT) * PITCH;
    cudaFuncSetAttribute(hm_gemm<NT, NA, NB, BF>,
                         cudaFuncAttributeMaxDynamicSharedMemorySize, 2 * STAGE);
    dim3 grid(N / NT, M / 128, batch);
    hm_gemm<NT, NA, NB, BF><<<grid, 256, 2 * STAGE>>>(
        (const uint16_t*)A0, (const uint16_t*)A1, (const uint16_t*)B0, (const uint16_t*)B1,
        Cf, C16, K, lda, ldb, ldc, sA, sB, sC, scale, mode, causal, aux, sAux);
}

extern "C" void kernel_launch(void* const* d_in, const int* in_sizes, int n_in,
                              void* d_out, int out_size)
{
    const float* hs   = (const float*)d_in[0];
    const float* wq   = (const float*)d_in[1];
    const float* wk   = (const float*)d_in[2];
    const float* wv   = (const float*)d_in[3];
    const float* wo   = (const float*)d_in[4];
    const float* kq1  = (const float*)d_in[5];
    const float* kq2  = (const float*)d_in[6];
    const float* kk1  = (const float*)d_in[7];
    const float* kk2  = (const float*)d_in[8];
    const float* scD  = (const float*)d_in[9];
    const float* ik   = (const float*)d_in[10];
    const float* scD2 = (const float*)d_in[11];

    float* out   = (float*)d_out;
    float* outO  = out;
    float* outH  = out + (size_t)S * D;
    float* outZ  = outH + (size_t)H * KD * HD;
    float* outQk = outZ + (size_t)H * KD;

    float* q = sym_f(g_q);  float* k = sym_f(g_k);  float* v = sym_f(g_v);
    bf16 *hsh = sym_b(g_hsh), *hsl = sym_b(g_hsl);
    fp16 *hs16 = sym_h(g_hs16);
    bf16 *qh = sym_b(g_qh), *ql = sym_b(g_ql), *kh = sym_b(g_kh), *kl = sym_b(g_kl);
    fp16 *q16 = sym_h(g_q16), *k16 = sym_h(g_k16);
    fp16 *vt16 = sym_h(g_vt16);
    bf16 *wqth = sym_b(g_wqth), *wqtl = sym_b(g_wqtl);
    bf16 *wkth = sym_b(g_wkth), *wktl = sym_b(g_wktl);
    fp16 *wvt16 = sym_h(g_wvt16), *wot16 = sym_h(g_wot16);
    fp16 *kq1t = sym_h(g_kq1t), *kk1t = sym_h(g_kk1t);
    fp16 *kq2t = sym_h(g_kq2t), *kk2t = sym_h(g_kk2t);
    fp16 *t116 = sym_h(g_t116);
    fp16 *ph = sym_h(g_ph);
    fp16 *ctx16 = sym_h(g_ctx16);
    float* kkA = sym_f(g_kkA);
    float* kker = sym_f(g_kker);
    float* logits = sym_f(g_logits);
    float* hp = sym_f(g_hpart);
    float* zp = sym_f(g_zpart);
    float* scores = sym_f(g_scores);
    float* elim = sym_f(g_elim);

    // ---- 0) operand prep ----
    split_hs_kernel<<<(S * D + 255) / 256, 256>>>(hs, hsh, hsl, hs16, S * D);
    {
        dim3 g(D / 32, D / 32, 1), b(32, 8);
        splitT_kernel<<<g, b>>>(wq, wqth, wqtl, D, D, 0, 0);
        splitT_kernel<<<g, b>>>(wk, wkth, wktl, D, D, 0, 0);
        splitT16_kernel<<<g, b>>>(wv, wvt16, D, D, 0, 0);
        splitT16_kernel<<<g, b>>>(wo, wot16, D, D, 0, 0);
    }
    {
        dim3 g(KH / 32, HD / 32, H), b(32, 8);
        splitT16_kernel<<<g, b>>>(kq1, kq1t, HD, KH, (long long)HD * KH, (long long)KH * HD);
        splitT16_kernel<<<g, b>>>(kk1, kk1t, HD, KH, (long long)HD * KH, (long long)KH * HD);
    }
    {
        dim3 g(KD / 32, KH / 32, H), b(32, 8);
        splitT16_kernel<<<g, b>>>(kq2, kq2t, KH, KD, (long long)KH * KD, (long long)KD * KH);
        splitT16_kernel<<<g, b>>>(kk2, kk2t, KH, KD, (long long)KH * KD, (long long)KD * KH);
    }

    // ---- 1) QKV projections ----
    launch_gemm<128, 2, 2, true>(hsh, hsl, wqth, wqtl, q, nullptr,
                                 S, D, D, D, D, D, 0, 0, 0, 1, 1.f, 0, 0);
    launch_gemm<128, 2, 2, true>(hsh, hsl, wkth, wktl, k, nullptr,
                                 S, D, D, D, D, D, 0, 0, 0, 1, 1.f, 0, 0);
    launch_gemm<128, 1, 1, false>(hs16, nullptr, wvt16, nullptr, v, nullptr,
                                  S, D, D, D, D, D, 0, 0, 0, 1, 1.f, 0, 0);

    // ---- 2) rotary ----
    rotary_split_kernel<<<(S * H * 64 + 255) / 256, 256>>>(q, k, qh, ql, kh, kl, q16, k16);

    // ---- 3) v^T fp16 per head ----
    {
        dim3 g(HD / 32, S / 32, H), b(32, 8);
        splitT16_kernel<<<g, b>>>(v, vt16, S, D, (long long)HD, (long long)HD * S);
    }

    // ---- 4) q_ker path (fp16 single) ----
    launch_gemm<128, 1, 1, false>(q16, nullptr, kq1t, nullptr, nullptr, t116,
                                  S, KH, HD, D, HD, KH,
                                  HD, (long long)KH * HD, (long long)S * KH, H, 1.f, 1, 0);
    launch_gemm<64, 1, 1, false>(t116, nullptr, kq2t, nullptr, outQk, nullptr,
                                 S, KD, KH, KH, KH, KD,
                                 (long long)S * KH, (long long)KD * KH, (long long)S * KD, H, 1.f, 2, 0);

    // ---- 5) k_ker path (fp16 single) ----
    launch_gemm<128, 1, 1, false>(k16, nullptr, kk1t, nullptr, nullptr, t116,
                                  S, KH, HD, D, HD, KH,
                                  HD, (long long)KH * HD, (long long)S * KH, H, 1.f, 1, 0);
    launch_gemm<64, 1, 1, false>(t116, nullptr, kk2t, nullptr, kkA, nullptr,
                                 S, KD, KH, KH, KH, KD,
                                 (long long)S * KH, (long long)KD * KH, (long long)S * KD, H, 1.f, 3, 0, scD, KD);

    // ---- 6) interaction -> kker ----
    {
        dim3 grid(S / 64, H);
        interact_kernel<<<grid, 256>>>(kkA, ik, scD2, kker);
    }

    // ---- 7) causal logits (bf16 3-pass: precision for top-k path) ----
    launch_gemm<128, 2, 2, true>(qh, ql, kh, kl, logits, nullptr,
                                 S, S, HD, D, D, S,
                                 HD, HD, (long long)S * S, H, 0.08838834764831843f, 0, 1);

    // ---- 8) fused softmax -> fp16 probs (FMA exp, no max shift) ----
    {
        dim3 grid(S, H);
        softmax_kernel<<<grid, 128>>>(logits, ph);
    }

    // ---- 9) scores / topk / hnew ----
    {
        dim3 grid(S / 256, H);
        scores_kernel<<<grid, 256>>>(ph, scores);
    }
    topk_kernel<<<H, 256>>>(scores, elim);
    {
        dim3 grid(H, 8);
        hnew_part<<<grid, 256>>>(kker, v, elim, hp, zp);
    }
    hnew_reduce<<<(H * KD * HD + 255) / 256, 256>>>(hp, zp, outH, outZ);

    // ---- 10) ctx = ph @ v16  (1-pass, causal K-limit) ----
    launch_gemm<128, 1, 1, false>(ph, nullptr, vt16, nullptr, nullptr, ctx16,
                                  S, HD, S, S, S, D,
                                  (long long)S * S, (long long)HD * S, (long long)HD, H, 1.f, 0, 2);

    // ---- 11) out = ctx @ wo (fp16 single) ----
    launch_gemm<128, 1, 1, false>(ctx16, nullptr, wot16, nullptr, outO, nullptr,
                                  S, D, D, D, D, D, 0, 0, 0, 1, 1.f, 0, 0);
}

// round 12
// speedup vs baseline: 3.4934x; 1.0643x over previous
#include <cuda_runtime.h>
#include <cuda_bf16.h>
#include <cuda_fp16.h>
#include <math.h>
#include <float.h>
#include <stdint.h>

#define S 2048
#define D 4096
#define H 32
#define HD 128
#define KH 128
#define KD 64
#define HEAVY 256
#define RECENT 256
#define NSEL (S - RECENT)   // 1792

typedef __nv_bfloat16 bf16;
typedef __half fp16;

// ---------------- scratch (device globals; zero-initialized at load) ----------------
__device__ float g_q[(size_t)S * D];
__device__ float g_k[(size_t)S * D];
__device__ float g_v[(size_t)S * D];
__device__ __align__(16) bf16 g_hsh[(size_t)S * D];
__device__ __align__(16) bf16 g_hsl[(size_t)S * D];
__device__ __align__(16) fp16 g_hs16[(size_t)S * D];
__device__ __align__(16) bf16 g_qh[(size_t)S * D];
__device__ __align__(16) bf16 g_ql[(size_t)S * D];
__device__ __align__(16) bf16 g_kh[(size_t)S * D];
__device__ __align__(16) bf16 g_kl[(size_t)S * D];
__device__ __align__(16) fp16 g_q16[(size_t)S * D];
__device__ __align__(16) fp16 g_k16[(size_t)S * D];
__device__ __align__(16) fp16 g_vt16[(size_t)H * HD * S];
__device__ __align__(16) bf16 g_wqth[(size_t)D * D];
__device__ __align__(16) bf16 g_wqtl[(size_t)D * D];
__device__ __align__(16) bf16 g_wkth[(size_t)D * D];
__device__ __align__(16) bf16 g_wktl[(size_t)D * D];
__device__ __align__(16) fp16 g_wvt16[(size_t)D * D];
__device__ __align__(16) fp16 g_wot16[(size_t)D * D];
__device__ __align__(16) fp16 g_kq1t[(size_t)H * KH * HD];
__device__ __align__(16) fp16 g_kk1t[(size_t)H * KH * HD];
__device__ __align__(16) fp16 g_kq2t[(size_t)H * KD * KH];
__device__ __align__(16) fp16 g_kk2t[(size_t)H * KD * KH];
__device__ __align__(16) fp16 g_t116[(size_t)H * S * KH];
__device__ float g_kkA[(size_t)H * S * KD];
__device__ float g_kker[(size_t)H * S * KD];
__device__ float g_logits[(size_t)H * S * S];   // 512 MB
__device__ __align__(16) fp16 g_ph[(size_t)H * S * S];        // 256 MB
__device__ __align__(16) fp16 g_ctx16[(size_t)S * D];
__device__ float g_hpart[(size_t)H * 8 * KD * HD];
__device__ float g_zpart[(size_t)H * 8 * KD];
__device__ float g_scores[H * S];
__device__ float g_elim[H * S];

__device__ __forceinline__ float gelu_f(float x) {
    return 0.5f * x * (1.0f + erff(x * 0.7071067811865476f));
}

// FMA-pipe exp: exp(x) = 2^n * exp(f*ln2), |f| <= 0.5, degree-5 Taylor (rel err ~2.4e-6)
__device__ __forceinline__ float fast_exp(float x) {
    float y = x * 1.4426950408889634f;
    float n = rintf(y);
    float t = (y - n) * 0.6931471805599453f;
    float p = 8.3333333e-3f;
    p = fmaf(p, t, 4.1666667e-2f);
    p = fmaf(p, t, 1.6666667e-1f);
    p = fmaf(p, t, 0.5f);
    p = fmaf(p, t, 1.0f);
    p = fmaf(p, t, 1.0f);
    int e = (int)n;
    e = e < -126 ? -126 : (e > 126 ? 126 : e);
    return p * __int_as_float((e + 127) << 23);
}

// ============================ PTX helpers ============================
__device__ __forceinline__ uint32_t smem_u32(const void* p) {
    uint32_t a;
    asm("{ .reg .u64 t; cvta.to.shared.u64 t, %1; cvt.u32.u64 %0, t; }" : "=r"(a) : "l"(p));
    return a;
}
__device__ __forceinline__ void cp16(uint32_t dst, const void* src) {
    asm volatile("cp.async.cg.shared.global [%0], [%1], 16;" :: "r"(dst), "l"(src));
}
#define CP_COMMIT() asm volatile("cp.async.commit_group;" ::: "memory")
#define CP_WAIT(n)  asm volatile("cp.async.wait_group %0;" :: "n"(n) : "memory")

#define LDSM4(r, addr) \
    asm volatile("ldmatrix.sync.aligned.m8n8.x4.shared.b16 {%0,%1,%2,%3}, [%4];" \
        : "=r"((r)[0]), "=r"((r)[1]), "=r"((r)[2]), "=r"((r)[3]) : "r"(addr))

#define MMA_BF(d, a, b) \
    asm volatile("mma.sync.aligned.m16n8k16.row.col.f32.bf16.bf16.f32 " \
        "{%0,%1,%2,%3}, {%4,%5,%6,%7}, {%8,%9}, {%0,%1,%2,%3};" \
        : "+f"((d)[0]), "+f"((d)[1]), "+f"((d)[2]), "+f"((d)[3]) \
        : "r"((a)[0]), "r"((a)[1]), "r"((a)[2]), "r"((a)[3]), "r"((b)[0]), "r"((b)[1]))

#define MMA_FP(d, a, b) \
    asm volatile("mma.sync.aligned.m16n8k16.row.col.f32.f16.f16.f32 " \
        "{%0,%1,%2,%3}, {%4,%5,%6,%7}, {%8,%9}, {%0,%1,%2,%3};" \
        : "+f"((d)[0]), "+f"((d)[1]), "+f"((d)[2]), "+f"((d)[3]) \
        : "r"((a)[0]), "r"((a)[1]), "r"((a)[2]), "r"((a)[3]), "r"((b)[0]), "r"((b)[1]))

// ============================ HMMA multi-pass GEMM ============================
// C[m,n] = epi( scale * sum_k (A0 [+A1])[m,k] * (B0 [+B1])[n,k] )  (B N-major)
// passes: (a0,b0); +(a0,b1) if NB==2; +(a1,b0) if NA==2.   (lo*lo dropped)
// modes: 0 none, 1 gelu, 2 abs(gelu), 3 |aux[n]|*gelu
// causal: 0 none; 1 logits (skip n0>m0 tiles, zero n>m); 2 K limited to m0+128.
// 3-stage cp.async pipeline, ONE __syncthreads per K-chunk (CUTLASS ordering).
#define PITCH 144          // 128 data bytes + 16 pad per smem row
#define BKE 64             // k elements per stage
#define NSTG 3             // pipeline stages

template <int NT, int NA, int NB, bool BF>
__global__ __launch_bounds__(256)
void hm_gemm(const uint16_t* __restrict__ A0, const uint16_t* __restrict__ A1,
             const uint16_t* __restrict__ B0, const uint16_t* __restrict__ B1,
             float* __restrict__ Cf, fp16* __restrict__ C16,
             int K, int lda, int ldb, int ldc,
             long long sA, long long sB, long long sC,
             float scale, int mode, int causal,
             const float* __restrict__ aux, long long sAux)
{
    constexpr int WN = NT / 2;         // warp n-extent (4x2 warp grid)
    constexpr int NT8 = WN / 8;        // n8 tiles per warp
    constexpr int ASZ = 128 * PITCH;
    constexpr int BSZ = NT * PITCH;
    constexpr int STAGE = NA * ASZ + NB * BSZ;
    extern __shared__ char smem[];

    const int tid = threadIdx.x;
    const int lane = tid & 31, wrp = tid >> 5;
    const int wm = wrp >> 1, wn = wrp & 1;
    const int m0 = blockIdx.y * 128;
    const int n0 = blockIdx.x * NT;
    if (causal == 1 && n0 > m0) return;

    const long long z = blockIdx.z;
    const uint16_t* Aop[2] = { A0 + z * sA, A1 ? A1 + z * sA : nullptr };
    const uint16_t* Bop[2] = { B0 + z * sB, B1 ? B1 + z * sB : nullptr };
    if (Cf) Cf += z * sC;
    if (C16) C16 += z * sC;
    if (aux) aux += z * sAux;

    const uint32_t sbase = smem_u32(smem);

    float acc[2][NT8][4];
#pragma unroll
    for (int i = 0; i < 2; i++)
#pragma unroll
        for (int j = 0; j < NT8; j++)
#pragma unroll
            for (int t = 0; t < 4; t++) acc[i][j][t] = 0.f;

    const int Keff = (causal == 2) ? (m0 + 128) : K;
    const int nch = Keff / BKE;

    auto load_stage = [&](int kc, int st) {
        const int k0 = kc * BKE;
        const uint32_t base = sbase + st * STAGE;
#pragma unroll
        for (int a = 0; a < NA; a++) {
            const uint32_t ab = base + a * ASZ;
#pragma unroll
            for (int it = 0; it < 4; it++) {
                int idx = tid + it * 256;              // 0..1023
                int r = idx >> 3, cb = (idx & 7) * 16;
                cp16(ab + r * PITCH + cb, Aop[a] + (size_t)(m0 + r) * lda + k0 + (cb >> 1));
            }
        }
#pragma unroll
        for (int b = 0; b < NB; b++) {
            const uint32_t bb = base + NA * ASZ + b * BSZ;
#pragma unroll
            for (int it = 0; it < NT / 32; it++) {
                int idx = tid + it * 256;
                int r = idx >> 3, cb = (idx & 7) * 16;
                cp16(bb + r * PITCH + cb, Bop[b] + (size_t)(n0 + r) * ldb + k0 + (cb >> 1));
            }
        }
        CP_COMMIT();
    };

    auto compute_stage = [&](int st) {
        const uint32_t base = sbase + st * STAGE;
#pragma unroll
        for (int ks = 0; ks < 4; ks++) {
            const uint32_t ksoff = ks * 32;           // bytes (16 elems)
            uint32_t af[NA][2][4];
#pragma unroll
            for (int a = 0; a < NA; a++) {
#pragma unroll
                for (int mt = 0; mt < 2; mt++) {
                    int row = wm * 32 + mt * 16 + (lane & 15);
                    uint32_t col = ksoff + ((lane & 16) ? 16 : 0);
                    LDSM4(af[a][mt], base + a * ASZ + row * PITCH + col);
                }
            }
            uint32_t bfr[NB][NT8][2];
#pragma unroll
            for (int b = 0; b < NB; b++) {
#pragma unroll
                for (int jp = 0; jp < NT8 / 2; jp++) {
                    int row = wn * WN + jp * 16 + (lane & 7) + ((lane & 16) >> 1);
                    uint32_t col = ksoff + ((lane & 8) ? 16 : 0);
                    uint32_t r4[4];
                    LDSM4(r4, base + NA * ASZ + b * BSZ + row * PITCH + col);
                    bfr[b][2 * jp][0] = r4[0]; bfr[b][2 * jp][1] = r4[1];
                    bfr[b][2 * jp + 1][0] = r4[2]; bfr[b][2 * jp + 1][1] = r4[3];
                }
            }
#pragma unroll
            for (int mt = 0; mt < 2; mt++)
#pragma unroll
                for (int nt = 0; nt < NT8; nt++) {
                    if (BF) { MMA_BF(acc[mt][nt], af[0][mt], bfr[0][nt]); }
                    else    { MMA_FP(acc[mt][nt], af[0][mt], bfr[0][nt]); }
                }
            if (NB == 2) {
#pragma unroll
                for (int mt = 0; mt < 2; mt++)
#pragma unroll
                    for (int nt = 0; nt < NT8; nt++) {
                        if (BF) { MMA_BF(acc[mt][nt], af[0][mt], bfr[NB - 1][nt]); }
                        else    { MMA_FP(acc[mt][nt], af[0][mt], bfr[NB - 1][nt]); }
                    }
            }
            if (NA == 2) {
#pragma unroll
                for (int mt = 0; mt < 2; mt++)
#pragma unroll
                    for (int nt = 0; nt < NT8; nt++) {
                        if (BF) { MMA_BF(acc[mt][nt], af[NA - 1][mt], bfr[0][nt]); }
                        else    { MMA_FP(acc[mt][nt], af[NA - 1][mt], bfr[0][nt]); }
                    }
            }
        }
    };

    // ---- prologue: fill stages 0,1; make stage 0 visible ----
    load_stage(0, 0);
    if (nch > 1) load_stage(1, 1); else CP_COMMIT();
    CP_WAIT(1);
    __syncthreads();

    // ---- mainloop: compute(i); load(i+2); wait(1); sync ----
    for (int i = 0; i < nch; i++) {
        compute_stage(i % NSTG);
        if (i + 2 < nch) load_stage(i + 2, (i + 2) % NSTG); else CP_COMMIT();
        CP_WAIT(1);
        __syncthreads();
    }

    // ---- epilogue ----
    const int r = lane >> 2, c = (lane & 3) * 2;
#pragma unroll
    for (int mt = 0; mt < 2; mt++) {
#pragma unroll
        for (int nt = 0; nt < NT8; nt++) {
#pragma unroll
            for (int e = 0; e < 4; e++) {
                const int m = m0 + wm * 32 + mt * 16 + r + ((e >> 1) ? 8 : 0);
                const int n = n0 + wn * WN + nt * 8 + c + (e & 1);
                float v = acc[mt][nt][e] * scale;
                if (mode == 1)      v = gelu_f(v);
                else if (mode == 2) v = fabsf(gelu_f(v));
                else if (mode == 3) v = fabsf(aux[n]) * gelu_f(v);
                if (causal == 1 && n > m) v = 0.f;
                const size_t o = (size_t)m * ldc + n;
                if (Cf)  Cf[o] = v;
                if (C16) C16[o] = __float2half_rn(v);
            }
        }
    }
}

// ---------------- hs: fp32 -> bf16 hi/lo + fp16 ----------------
__global__ void split_hs_kernel(const float* __restrict__ x, bf16* __restrict__ hi,
                                bf16* __restrict__ lo, fp16* __restrict__ h16, int n)
{
    int i = blockIdx.x * blockDim.x + threadIdx.x;
    if (i >= n) return;
    float v = x[i];
    bf16 h = __float2bfloat16(v);
    hi[i] = h;
    lo[i] = __float2bfloat16(v - __bfloat162float(h));
    h16[i] = __float2half_rn(v);
}

// ---------------- split+transpose fp32 -> bf16 hi/lo (for wq, wk) ----------------
__global__ void splitT_kernel(const float* __restrict__ in, bf16* __restrict__ oh,
                              bf16* __restrict__ ol, int R, int ldin,
                              long long sIn, long long sOut)
{
    in += (long long)blockIdx.z * sIn;
    oh += (long long)blockIdx.z * sOut;
    ol += (long long)blockIdx.z * sOut;
    __shared__ float t[32][33];
    int r0 = blockIdx.y * 32, c0 = blockIdx.x * 32;
    int tx = threadIdx.x, ty = threadIdx.y;  // (32, 8)
#pragma unroll
    for (int i = 0; i < 4; i++)
        t[ty + 8 * i][tx] = in[(size_t)(r0 + ty + 8 * i) * ldin + c0 + tx];
    __syncthreads();
#pragma unroll
    for (int i = 0; i < 4; i++) {
        int oc = ty + 8 * i;
        float v = t[tx][oc];
        size_t o = (size_t)(c0 + oc) * R + r0 + tx;
        bf16 h = __float2bfloat16(v);
        oh[o] = h;
        ol[o] = __float2bfloat16(v - __bfloat162float(h));
    }
}

// ---------------- transpose fp32 -> fp16 single ----------------
__global__ void splitT16_kernel(const float* __restrict__ in, fp16* __restrict__ o16,
                                int R, int ldin, long long sIn, long long sOut)
{
    in += (long long)blockIdx.z * sIn;
    o16 += (long long)blockIdx.z * sOut;
    __shared__ float t[32][33];
    int r0 = blockIdx.y * 32, c0 = blockIdx.x * 32;
    int tx = threadIdx.x, ty = threadIdx.y;
#pragma unroll
    for (int i = 0; i < 4; i++)
        t[ty + 8 * i][tx] = in[(size_t)(r0 + ty + 8 * i) * ldin + c0 + tx];
    __syncthreads();
#pragma unroll
    for (int i = 0; i < 4; i++) {
        int oc = ty + 8 * i;
        o16[(size_t)(c0 + oc) * R + r0 + tx] = __float2half_rn(t[tx][oc]);
    }
}

// ---------------- rotary: fp32 q,k -> bf16 hi/lo + fp16 ----------------
__global__ void rotary_split_kernel(const float* __restrict__ q, const float* __restrict__ k,
                                    bf16* __restrict__ qh, bf16* __restrict__ ql,
                                    bf16* __restrict__ kh, bf16* __restrict__ kl,
                                    fp16* __restrict__ q16, fp16* __restrict__ k16)
{
    int idx = blockIdx.x * blockDim.x + threadIdx.x;
    if (idx >= S * H * 64) return;
    int i = idx & 63;
    int h = (idx >> 6) & 31;
    int s = idx >> 11;
    float inv = expf(-9.210340371976184f * (float)i / 64.0f);
    float ang = (float)s * inv;
    float sn, c;
    sincosf(ang, &sn, &c);
    long long base = (long long)s * D + h * HD;
    {
        float x1 = q[base + i], x2 = q[base + 64 + i];
        float r1 = x1 * c - x2 * sn;
        float r2 = x2 * c + x1 * sn;
        bf16 h1 = __float2bfloat16(r1); qh[base + i] = h1;      ql[base + i] = __float2bfloat16(r1 - __bfloat162float(h1));
        bf16 h2 = __float2bfloat16(r2); qh[base + 64 + i] = h2; ql[base + 64 + i] = __float2bfloat16(r2 - __bfloat162float(h2));
        q16[base + i] = __float2half_rn(r1);
        q16[base + 64 + i] = __float2half_rn(r2);
    }
    {
        float x1 = k[base + i], x2 = k[base + 64 + i];
        float r1 = x1 * c - x2 * sn;
        float r2 = x2 * c + x1 * sn;
        bf16 h1 = __float2bfloat16(r1); kh[base + i] = h1;      kl[base + i] = __float2bfloat16(r1 - __bfloat162float(h1));
        bf16 h2 = __float2bfloat16(r2); kh[base + 64 + i] = h2; kl[base + 64 + i] = __float2bfloat16(r2 - __bfloat162float(h2));
        k16[base + i] = __float2half_rn(r1);
        k16[base + 64 + i] = __float2half_rn(r2);
    }
}

// ---------------- k_ker interaction: kker = |kkA + (kkA @ ik) * scD2| ----------------
__global__ __launch_bounds__(256)
void interact_kernel(const float* __restrict__ kkA, const float* __restrict__ ik,
                     const float* __restrict__ sc2, float* __restrict__ kker)
{
    int h = blockIdx.y;
    int s0 = blockIdx.x * 64;
    int tid = threadIdx.x;
    __shared__ float sIK[KD][KD];
    __shared__ float sA[64][KD + 1];
    for (int idx = tid; idx < KD * KD; idx += 256)
        sIK[idx >> 6][idx & 63] = ik[(size_t)h * KD * KD + idx];
    for (int idx = tid; idx < 64 * KD; idx += 256) {
        int r = idx >> 6, e = idx & 63;
        sA[r][e] = kkA[((size_t)h * S + s0 + r) * KD + e];
    }
    __syncthreads();
    int r = tid >> 2;
    int f0 = (tid & 3) * 16;
#pragma unroll
    for (int ff = 0; ff < 16; ff++) {
        int f = f0 + ff;
        float sum = 0.f;
#pragma unroll
        for (int e = 0; e < KD; e++) sum += sA[r][e] * sIK[e][f];
        float val = sA[r][f] + sum * sc2[h * KD + f];
        kker[((size_t)h * S + s0 + r) * KD + f] = fabsf(val);
    }
}

// ---------------- fused causal softmax (no max shift, FMA exp): fp32 logits -> fp16 probs ----------------
__global__ void softmax_kernel(const float* __restrict__ logits, fp16* __restrict__ ph)
{
    int q = blockIdx.x;
    int h = blockIdx.y;
    const float* row = logits + ((size_t)h * S + q) * S;
    fp16* rh = ph + ((size_t)h * S + q) * S;
    int len = q + 1;
    int tid = threadIdx.x;
    __shared__ float red[128];

    float vals[16];
    float sum = 0.f;
#pragma unroll
    for (int i = 0; i < 16; i++) {
        int k = tid + i * 128;
        float e = 0.f;
        if (k < len) e = fast_exp(row[k]);
        vals[i] = e;
        sum += e;
    }
    red[tid] = sum; __syncthreads();
    for (int off = 64; off > 0; off >>= 1) {
        if (tid < off) red[tid] += red[tid + off];
        __syncthreads();
    }
    float inv = 1.0f / red[0];
#pragma unroll
    for (int i = 0; i < 16; i++) {
        int k = tid + i * 128;
        if (k < len) rh[k] = __float2half_rn(vals[i] * inv);
    }
}

// ---------------- column sums of probs (upper triangle is exactly 0) ----------------
__global__ void scores_kernel(const fp16* __restrict__ ph, float* __restrict__ scores)
{
    int h = blockIdx.y;
    int k = blockIdx.x * 256 + threadIdx.x;
    const fp16* p1 = ph + (size_t)h * S * S + k;
    float s = 0.f;
    for (int q = 0; q < S; q++)
        s += __half2float(p1[(size_t)q * S]);
    scores[h * S + k] = s;
}

// ---------------- top-HEAVY selection -> elim mask ----------------
__global__ __launch_bounds__(256)
void topk_kernel(const float* __restrict__ scores, float* __restrict__ elim)
{
    int h = blockIdx.x;
    int tid = threadIdx.x;
    __shared__ float sv[NSEL];
    __shared__ float rv[256];
    __shared__ int   ri[256];
    for (int j = tid; j < NSEL; j += 256) sv[j] = scores[h * S + j];
    for (int s = tid; s < S; s += 256) elim[h * S + s] = (s <= NSEL) ? 1.f : 0.f;
    __syncthreads();
    for (int iter = 0; iter < HEAVY; iter++) {
        float best = -1.f; int bi = 0x7fffffff;
        for (int j = tid; j < NSEL; j += 256) {
            float vv = sv[j];
            if (vv > best) { best = vv; bi = j; }
        }
        rv[tid] = best; ri[tid] = bi; __syncthreads();
        for (int off = 128; off > 0; off >>= 1) {
            if (tid < off) {
                float ov = rv[tid + off]; int oi = ri[tid + off];
                if (ov > rv[tid] || (ov == rv[tid] && oi < ri[tid])) { rv[tid] = ov; ri[tid] = oi; }
            }
            __syncthreads();
        }
        if (tid == 0) { int b = ri[0]; elim[h * S + b] = 0.f; sv[b] = -2.f; }
        __syncthreads();
    }
}

// ---------------- H_new / z_new partials over s-chunks ----------------
__global__ __launch_bounds__(256)
void hnew_part(const float* __restrict__ kker, const float* __restrict__ v,
               const float* __restrict__ elim,
               float* __restrict__ hp, float* __restrict__ zp)
{
    int h = blockIdx.x;
    int ch = blockIdx.y;   // 0..7, each 256 rows
    int tid = threadIdx.x;
    __shared__ float skk[32][KD];
    __shared__ float sv[32][HD];
    int dg = tid & 15;
    int eg = tid >> 4;
    float acc[4][8];
#pragma unroll
    for (int e = 0; e < 4; e++)
#pragma unroll
        for (int d = 0; d < 8; d++) acc[e][d] = 0.f;
    float zacc = 0.f;

    const float* kkh = kker + (size_t)h * S * KD;
    const float* vh  = v + h * HD;
    const int sBeg = ch * 256, sEnd = sBeg + 256;
    for (int s0 = sBeg; s0 < sEnd; s0 += 32) {
        for (int idx = tid; idx < 32 * KD; idx += 256) {
            int si = idx >> 6; int e = idx & 63;
            skk[si][e] = kkh[(size_t)(s0 + si) * KD + e] * elim[h * S + s0 + si];
        }
        for (int idx = tid; idx < 32 * HD; idx += 256) {
            int si = idx >> 7; int d = idx & 127;
            sv[si][d] = vh[(size_t)(s0 + si) * D + d];
        }
        __syncthreads();
        if (tid < KD) {
#pragma unroll
            for (int si = 0; si < 32; si++) zacc += skk[si][tid];
        }
#pragma unroll 4
        for (int si = 0; si < 32; si++) {
            float ke[4], vd[8];
#pragma unroll
            for (int e = 0; e < 4; e++) ke[e] = skk[si][eg * 4 + e];
#pragma unroll
            for (int d = 0; d < 8; d++) vd[d] = sv[si][dg * 8 + d];
#pragma unroll
            for (int e = 0; e < 4; e++)
#pragma unroll
                for (int d = 0; d < 8; d++)
                    acc[e][d] += ke[e] * vd[d];
        }
        __syncthreads();
    }
    float* hout = hp + ((size_t)h * 8 + ch) * KD * HD;
#pragma unroll
    for (int e = 0; e < 4; e++)
#pragma unroll
        for (int d = 0; d < 8; d++)
            hout[(eg * 4 + e) * HD + dg * 8 + d] = acc[e][d];
    if (tid < KD) zp[((size_t)h * 8 + ch) * KD + tid] = zacc;
}

__global__ void hnew_reduce(const float* __restrict__ hp, const float* __restrict__ zp,
                            float* __restrict__ Hout, float* __restrict__ zout)
{
    int i = blockIdx.x * 256 + threadIdx.x;   // over H*KD*HD
    if (i >= H * KD * HD) return;
    int h = i / (KD * HD);
    int r = i % (KD * HD);
    float s = 0.f;
#pragma unroll
    for (int c = 0; c < 8; c++) s += hp[((size_t)h * 8 + c) * KD * HD + r];
    Hout[i] = s;
    if (i < H * KD) {
        int hh = i / KD, e = i % KD;
        float z = 0.f;
#pragma unroll
        for (int c = 0; c < 8; c++) z += zp[((size_t)hh * 8 + c) * KD + e];
        zout[i] = z;
    }
}

// ---------------- host side ----------------
template <typename T>
static float* sym_f(T& sym) { void* p = nullptr; cudaGetSymbolAddress(&p, sym); return (float*)p; }
template <typename T>
static bf16* sym_b(T& sym) { void* p = nullptr; cudaGetSymbolAddress(&p, sym); return (bf16*)p; }
template <typename T>
static fp16* sym_h(T& sym) { void* p = nullptr; cudaGetSymbolAddress(&p, sym); return (fp16*)p; }

template <int NT, int NA, int NB, bool BF>
static void launch_gemm(const void* A0, const void* A1, const void* B0, const void* B1,
                        float* Cf, fp16* C16,
                        int M, int N, int K, int lda, int ldb, int ldc,
                        long long sA, long long sB, long long sC, int batch,
                        float scale, int mode, int causal,
                        const float* aux = nullptr, long long sAux = 0)
{
    constexpr int STAGE = (NA * 128 + NB * NT) * PITCH;
    cudaFuncSetAttribute(hm_gemm<NT, NA, NB, BF>,
                         cudaFuncAttributeMaxDynamicSharedMemorySize, NSTG * STAGE);
    dim3 grid(N / NT, M / 128, batch);
    hm_gemm<NT, NA, NB, BF><<<grid, 256, NSTG * STAGE>>>(
        (const uint16_t*)A0, (const uint16_t*)A1, (const uint16_t*)B0, (const uint16_t*)B1,
        Cf, C16, K, lda, ldb, ldc, sA, sB, sC, scale, mode, causal, aux, sAux);
}

extern "C" void kernel_launch(void* const* d_in, const int* in_sizes, int n_in,
                              void* d_out, int out_size)
{
    const float* hs   = (const float*)d_in[0];
    const float* wq   = (const float*)d_in[1];
    const float* wk   = (const float*)d_in[2];
    const float* wv   = (const float*)d_in[3];
    const float* wo   = (const float*)d_in[4];
    const float* kq1  = (const float*)d_in[5];
    const float* kq2  = (const float*)d_in[6];
    const float* kk1  = (const float*)d_in[7];
    const float* kk2  = (const float*)d_in[8];
    const float* scD  = (const float*)d_in[9];
    const float* ik   = (const float*)d_in[10];
    const float* scD2 = (const float*)d_in[11];

    float* out   = (float*)d_out;
    float* outO  = out;
    float* outH  = out + (size_t)S * D;
    float* outZ  = outH + (size_t)H * KD * HD;
    float* outQk = outZ + (size_t)H * KD;

    float* q = sym_f(g_q);  float* k = sym_f(g_k);  float* v = sym_f(g_v);
    bf16 *hsh = sym_b(g_hsh), *hsl = sym_b(g_hsl);
    fp16 *hs16 = sym_h(g_hs16);
    bf16 *qh = sym_b(g_qh), *ql = sym_b(g_ql), *kh = sym_b(g_kh), *kl = sym_b(g_kl);
    fp16 *q16 = sym_h(g_q16), *k16 = sym_h(g_k16);
    fp16 *vt16 = sym_h(g_vt16);
    bf16 *wqth = sym_b(g_wqth), *wqtl = sym_b(g_wqtl);
    bf16 *wkth = sym_b(g_wkth), *wktl = sym_b(g_wktl);
    fp16 *wvt16 = sym_h(g_wvt16), *wot16 = sym_h(g_wot16);
    fp16 *kq1t = sym_h(g_kq1t), *kk1t = sym_h(g_kk1t);
    fp16 *kq2t = sym_h(g_kq2t), *kk2t = sym_h(g_kk2t);
    fp16 *t116 = sym_h(g_t116);
    fp16 *ph = sym_h(g_ph);
    fp16 *ctx16 = sym_h(g_ctx16);
    float* kkA = sym_f(g_kkA);
    float* kker = sym_f(g_kker);
    float* logits = sym_f(g_logits);
    float* hp = sym_f(g_hpart);
    float* zp = sym_f(g_zpart);
    float* scores = sym_f(g_scores);
    float* elim = sym_f(g_elim);

    // ---- 0) operand prep ----
    split_hs_kernel<<<(S * D + 255) / 256, 256>>>(hs, hsh, hsl, hs16, S * D);
    {
        dim3 g(D / 32, D / 32, 1), b(32, 8);
        splitT_kernel<<<g, b>>>(wq, wqth, wqtl, D, D, 0, 0);
        splitT_kernel<<<g, b>>>(wk, wkth, wktl, D, D, 0, 0);
        splitT16_kernel<<<g, b>>>(wv, wvt16, D, D, 0, 0);
        splitT16_kernel<<<g, b>>>(wo, wot16, D, D, 0, 0);
    }
    {
        dim3 g(KH / 32, HD / 32, H), b(32, 8);
        splitT16_kernel<<<g, b>>>(kq1, kq1t, HD, KH, (long long)HD * KH, (long long)KH * HD);
        splitT16_kernel<<<g, b>>>(kk1, kk1t, HD, KH, (long long)HD * KH, (long long)KH * HD);
    }
    {
        dim3 g(KD / 32, KH / 32, H), b(32, 8);
        splitT16_kernel<<<g, b>>>(kq2, kq2t, KH, KD, (long long)KH * KD, (long long)KD * KH);
        splitT16_kernel<<<g, b>>>(kk2, kk2t, KH, KD, (long long)KH * KD, (long long)KD * KH);
    }

    // ---- 1) QKV projections ----
    launch_gemm<128, 2, 2, true>(hsh, hsl, wqth, wqtl, q, nullptr,
                                 S, D, D, D, D, D, 0, 0, 0, 1, 1.f, 0, 0);
    launch_gemm<128, 2, 2, true>(hsh, hsl, wkth, wktl, k, nullptr,
                                 S, D, D, D, D, D, 0, 0, 0, 1, 1.f, 0, 0);
    launch_gemm<128, 1, 1, false>(hs16, nullptr, wvt16, nullptr, v, nullptr,
                                  S, D, D, D, D, D, 0, 0, 0, 1, 1.f, 0, 0);

    // ---- 2) rotary ----
    rotary_split_kernel<<<(S * H * 64 + 255) / 256, 256>>>(q, k, qh, ql, kh, kl, q16, k16);

    // ---- 3) v^T fp16 per head ----
    {
        dim3 g(HD / 32, S / 32, H), b(32, 8);
        splitT16_kernel<<<g, b>>>(v, vt16, S, D, (long long)HD, (long long)HD * S);
    }

    // ---- 4) q_ker path (fp16 single) ----
    launch_gemm<128, 1, 1, false>(q16, nullptr, kq1t, nullptr, nullptr, t116,
                                  S, KH, HD, D, HD, KH,
                                  HD, (long long)KH * HD, (long long)S * KH, H, 1.f, 1, 0);
    launch_gemm<64, 1, 1, false>(t116, nullptr, kq2t, nullptr, outQk, nullptr,
                                 S, KD, KH, KH, KH, KD,
                                 (long long)S * KH, (long long)KD * KH, (long long)S * KD, H, 1.f, 2, 0);

    // ---- 5) k_ker path (fp16 single) ----
    launch_gemm<128, 1, 1, false>(k16, nullptr, kk1t, nullptr, nullptr, t116,
                                  S, KH, HD, D, HD, KH,
                                  HD, (long long)KH * HD, (long long)S * KH, H, 1.f, 1, 0);
    launch_gemm<64, 1, 1, false>(t116, nullptr, kk2t, nullptr, kkA, nullptr,
                                 S, KD, KH, KH, KH, KD,
                                 (long long)S * KH, (long long)KD * KH, (long long)S * KD, H, 1.f, 3, 0, scD, KD);

    // ---- 6) interaction -> kker ----
    {
        dim3 grid(S / 64, H);
        interact_kernel<<<grid, 256>>>(kkA, ik, scD2, kker);
    }

    // ---- 7) causal logits (bf16 3-pass: precision for top-k path) ----
    launch_gemm<128, 2, 2, true>(qh, ql, kh, kl, logits, nullptr,
                                 S, S, HD, D, D, S,
                                 HD, HD, (long long)S * S, H, 0.08838834764831843f, 0, 1);

    // ---- 8) fused softmax -> fp16 probs (FMA exp, no max shift) ----
    {
        dim3 grid(S, H);
        softmax_kernel<<<grid, 128>>>(logits, ph);
    }

    // ---- 9) scores / topk / hnew ----
    {
        dim3 grid(S / 256, H);
        scores_kernel<<<grid, 256>>>(ph, scores);
    }
    topk_kernel<<<H, 256>>>(scores, elim);
    {
        dim3 grid(H, 8);
        hnew_part<<<grid, 256>>>(kker, v, elim, hp, zp);
    }
    hnew_reduce<<<(H * KD * HD + 255) / 256, 256>>>(hp, zp, outH, outZ);

    // ---- 10) ctx = ph @ v16  (1-pass, causal K-limit) ----
    launch_gemm<128, 1, 1, false>(ph, nullptr, vt16, nullptr, nullptr, ctx16,
                                  S, HD, S, S, S, D,
                                  (long long)S * S, (long long)HD * S, (long long)HD, H, 1.f, 0, 2);

    // ---- 11) out = ctx @ wo (fp16 single) ----
    launch_gemm<128, 1, 1, false>(ctx16, nullptr, wot16, nullptr, outO, nullptr,
                                  S, D, D, D, D, D, 0, 0, 0, 1, 1.f, 0, 0);
}